// round 1
// baseline (speedup 1.0000x reference)
#include <cuda_runtime.h>
#include <math.h>
#include <stdint.h>

// ---------------- problem dims ----------------
#define T_    1024
#define B_    4
#define E_    512
#define H_    8
#define D_    64
#define DFF_  2048
#define NTOK  4096            // T_*B_
#define PLEN  2047            // 2T-1
#define KCONV 31

// ---------------- scratch (device globals; no allocation) ----------------
__device__ float g_ff[NTOK * DFF_];               // FFN hidden / conv pw1 out (reused)
__device__ float g_x1[NTOK * E_];                 // after macaron FFN   (also reused as x4)
__device__ float g_x2[NTOK * E_];                 // after attention
__device__ float g_x3[NTOK * E_];                 // after conv module
__device__ float g_qkv[NTOK * 3 * E_];
__device__ float g_pproj[PLEN * E_];
__device__ float g_scores[32ull * T_ * T_];       // (B*H, T, T)
__device__ float g_ctx[NTOK * E_];
__device__ float g_glu[NTOK * E_];
__device__ float g_dsw[NTOK * E_];

__device__ __forceinline__ float sigmoidf_(float x) { return 1.f / (1.f + __expf(-x)); }

// ---------------- generic NT GEMM: C = epi(A(MxK) * B(NxK)^T + bias) ----------------
enum { EPI_NONE = 0, EPI_DSWISH = 1, EPI_RES = 2 };

template <int EPI>
__global__ void gemm_nt_kernel(const float* __restrict__ A, const float* __restrict__ Bm,
                               const float* __restrict__ bias, const float* __restrict__ res,
                               float* __restrict__ C, int M, int N, int K)
{
    __shared__ float As[16][68];   // As[k][m], padded for float4-aligned, low-conflict access
    __shared__ float Bs[16][68];   // Bs[k][n]
    const int tid = threadIdx.x;               // 256 threads
    const int m0 = blockIdx.y * 64, n0 = blockIdx.x * 64;
    const int tm = (tid >> 4) << 2;
    const int tn = (tid & 15) << 2;
    float acc[4][4] = {};

    for (int k0 = 0; k0 < K; k0 += 16) {
#pragma unroll
        for (int r = 0; r < 4; r++) {
            int i = tid + r * 256;             // 0..1023 covers 64x16
            int m = i >> 4, k = i & 15;
            int gm = m0 + m;
            As[k][m] = (gm < M) ? A[(size_t)gm * K + k0 + k] : 0.f;
            int gn = n0 + m;
            Bs[k][m] = (gn < N) ? Bm[(size_t)gn * K + k0 + k] : 0.f;
        }
        __syncthreads();
#pragma unroll
        for (int k = 0; k < 16; k++) {
            float4 a = *reinterpret_cast<const float4*>(&As[k][tm]);
            float4 b = *reinterpret_cast<const float4*>(&Bs[k][tn]);
            float av[4] = {a.x, a.y, a.z, a.w};
            float bv[4] = {b.x, b.y, b.z, b.w};
#pragma unroll
            for (int x = 0; x < 4; x++)
#pragma unroll
                for (int y = 0; y < 4; y++) acc[x][y] += av[x] * bv[y];
        }
        __syncthreads();
    }

#pragma unroll
    for (int x = 0; x < 4; x++) {
        int gm = m0 + tm + x;
        if (gm >= M) continue;
#pragma unroll
        for (int y = 0; y < 4; y++) {
            int gn = n0 + tn + y;
            if (gn >= N) continue;
            float v = acc[x][y];
            if (bias) v += bias[gn];
            if (EPI == EPI_DSWISH) v = v * sigmoidf_(v - 1.f);
            if (EPI == EPI_RES)    v += res[(size_t)gm * N + gn];
            C[(size_t)gm * N + gn] = v;
        }
    }
}

// ---------------- attention scores: scores = (q+u)K^T + rel_shift((q+v)P) ----------------
// fused rel_shift: scores[b,h,i,j] = sum_d (q+u)[i,d]k[j,d] + sum_d (q+v)[i,d]p[d, T-1-i+j]
__global__ void attn_scores_kernel(const float* __restrict__ qkv,
                                   const float* __restrict__ pproj,
                                   const float* __restrict__ u,
                                   const float* __restrict__ v,
                                   float* __restrict__ scores)
{
    extern __shared__ float sm[];
    float* Qu = sm;                 // [64][65]
    float* Qv = Qu + 64 * 65;       // [64][65]
    float* Kt = Qv + 64 * 65;       // [64][65]   Kt[j][d]
    float* Ps = Kt + 64 * 65;       // [64][128]  Ps[d][mm], mm in [0,126]

    const int bh = blockIdx.z;
    const int b = bh >> 3, h = bh & 7;
    const int i0 = blockIdx.y * 64, j0 = blockIdx.x * 64;
    const int tid = threadIdx.x;
    const float scale = 0.125f;     // D^-0.5

    for (int idx = tid; idx < 64 * 64; idx += 256) {
        int li = idx >> 6, d = idx & 63;
        float q = qkv[(size_t)((i0 + li) * B_ + b) * (3 * E_) + h * 64 + d] * scale;
        Qu[li * 65 + d] = q + u[h * 64 + d];
        Qv[li * 65 + d] = q + v[h * 64 + d];
        Kt[li * 65 + d] = qkv[(size_t)((j0 + li) * B_ + b) * (3 * E_) + E_ + h * 64 + d];
    }
    const int m_min = (T_ - 1) - (i0 + 63) + j0;      // >= 0, m_min+126 <= 2046
    for (int idx = tid; idx < 64 * 127; idx += 256) {
        int d = idx / 127, mm = idx % 127;
        Ps[d * 128 + mm] = pproj[(size_t)(m_min + mm) * E_ + h * 64 + d];
    }
    __syncthreads();

    const int tm = (tid >> 4) << 2;
    const int tn = (tid & 15) << 2;
    const int base = 63 - tm + tn;   // mm for (ii=0,jj=0); mm = base + jj - ii
    float acc[4][4] = {};

#pragma unroll 8
    for (int d = 0; d < 64; d++) {
        float a[4], c[4], bb[4], p7[7];
#pragma unroll
        for (int ii = 0; ii < 4; ii++) {
            a[ii] = Qu[(tm + ii) * 65 + d];
            c[ii] = Qv[(tm + ii) * 65 + d];
        }
#pragma unroll
        for (int jj = 0; jj < 4; jj++) bb[jj] = Kt[(tn + jj) * 65 + d];
#pragma unroll
        for (int t = 0; t < 7; t++) p7[t] = Ps[d * 128 + base + t - 3];
#pragma unroll
        for (int ii = 0; ii < 4; ii++)
#pragma unroll
            for (int jj = 0; jj < 4; jj++)
                acc[ii][jj] += a[ii] * bb[jj] + c[ii] * p7[jj - ii + 3];
    }

    const size_t ob = ((size_t)bh * T_ + i0) * T_ + j0;
#pragma unroll
    for (int ii = 0; ii < 4; ii++)
#pragma unroll
        for (int jj = 0; jj < 4; jj++)
            scores[ob + (size_t)(tm + ii) * T_ + tn + jj] = acc[ii][jj];
}

// ---------------- softmax over rows of length 1024 (in place) ----------------
__global__ void softmax_kernel(float* __restrict__ s)
{
    __shared__ float red[8];
    __shared__ float red2[8];
    const int tid = threadIdx.x;
    float* p = s + (size_t)blockIdx.x * 1024;
    float v[4];
    float m = -1e30f;
#pragma unroll
    for (int i = 0; i < 4; i++) { v[i] = p[tid + i * 256]; m = fmaxf(m, v[i]); }
#pragma unroll
    for (int o = 16; o > 0; o >>= 1) m = fmaxf(m, __shfl_xor_sync(0xffffffffu, m, o));
    if ((tid & 31) == 0) red[tid >> 5] = m;
    __syncthreads();
    m = red[0];
#pragma unroll
    for (int i = 1; i < 8; i++) m = fmaxf(m, red[i]);

    float sum = 0.f;
#pragma unroll
    for (int i = 0; i < 4; i++) { v[i] = __expf(v[i] - m); sum += v[i]; }
#pragma unroll
    for (int o = 16; o > 0; o >>= 1) sum += __shfl_xor_sync(0xffffffffu, sum, o);
    if ((tid & 31) == 0) red2[tid >> 5] = sum;
    __syncthreads();
    sum = red2[0];
#pragma unroll
    for (int i = 1; i < 8; i++) sum += red2[i];
    float inv = 1.f / sum;
#pragma unroll
    for (int i = 0; i < 4; i++) p[tid + i * 256] = v[i] * inv;
}

// ---------------- attn @ V -> ctx in (T,B,E) layout ----------------
__global__ void attn_out_kernel(const float* __restrict__ scores,
                                const float* __restrict__ qkv,
                                float* __restrict__ ctx)
{
    __shared__ float As[64][33];    // attn[i][k] tile 64x32
    __shared__ float Bs[32][68];    // val[k][d]  tile 32x64
    const int bh = blockIdx.y;
    const int b = bh >> 3, h = bh & 7;
    const int i0 = blockIdx.x * 64;
    const int tid = threadIdx.x;
    const float* S = scores + ((size_t)bh * T_ + i0) * T_;
    const int tm = (tid >> 4) << 2;
    const int tn = (tid & 15) << 2;
    float acc[4][4] = {};

    for (int k0 = 0; k0 < T_; k0 += 32) {
#pragma unroll
        for (int r = 0; r < 8; r++) {
            int idx = tid + r * 256;           // 0..2047 covers 64x32
            int ii = idx >> 5, kk = idx & 31;
            As[ii][kk] = S[(size_t)ii * T_ + k0 + kk];
        }
#pragma unroll
        for (int r = 0; r < 8; r++) {
            int idx = tid + r * 256;           // 0..2047 covers 32x64
            int kk = idx >> 6, d = idx & 63;
            Bs[kk][d] = qkv[(size_t)((k0 + kk) * B_ + b) * (3 * E_) + 2 * E_ + h * 64 + d];
        }
        __syncthreads();
#pragma unroll
        for (int kk = 0; kk < 32; kk++) {
            float a[4];
            float4 bv4 = *reinterpret_cast<const float4*>(&Bs[kk][tn]);
            float bv[4] = {bv4.x, bv4.y, bv4.z, bv4.w};
#pragma unroll
            for (int x = 0; x < 4; x++) a[x] = As[tm + x][kk];
#pragma unroll
            for (int x = 0; x < 4; x++)
#pragma unroll
                for (int y = 0; y < 4; y++) acc[x][y] += a[x] * bv[y];
        }
        __syncthreads();
    }
#pragma unroll
    for (int x = 0; x < 4; x++) {
        int gi = i0 + tm + x;
#pragma unroll
        for (int y = 0; y < 4; y++)
            ctx[(size_t)(gi * B_ + b) * E_ + h * 64 + tn + y] = acc[x][y];
    }
}

// ---------------- GLU over channel dim ----------------
__global__ void glu_kernel(const float* __restrict__ y, float* __restrict__ out)
{
    int idx = blockIdx.x * 256 + threadIdx.x;           // over NTOK*E_
    if (idx >= NTOK * E_) return;
    int r = idx >> 9, c = idx & 511;
    float a = y[(size_t)r * 1024 + c];
    float g = y[(size_t)r * 1024 + 512 + c];
    out[idx] = a * sigmoidf_(g);
}

// ---------------- depthwise conv (K=31, pad=15) + DoubleSwish ----------------
__global__ void dwconv_kernel(const float* __restrict__ x, const float* __restrict__ w,
                              const float* __restrict__ bias, float* __restrict__ out)
{
    int idx = blockIdx.x * 256 + threadIdx.x;           // over NTOK*E_
    if (idx >= NTOK * E_) return;
    int c = idx & 511;
    int tb = idx >> 9;
    int t = tb >> 2, b = tb & 3;
    float acc = bias[c];
#pragma unroll
    for (int k = 0; k < KCONV; k++) {
        int tt = t + k - 15;
        if (tt >= 0 && tt < T_)
            acc += x[(size_t)(tt * B_ + b) * E_ + c] * w[c * KCONV + k];
    }
    out[idx] = acc * sigmoidf_(acc - 1.f);
}

// ---------------- BasicNorm ----------------
__global__ void basic_norm_kernel(const float* __restrict__ x, const float* __restrict__ leps,
                                  float* __restrict__ out)
{
    __shared__ float red[8];
    const int tid = threadIdx.x;
    const float* p = x + (size_t)blockIdx.x * E_;
    float v0 = p[tid], v1 = p[tid + 256];
    float ss = v0 * v0 + v1 * v1;
#pragma unroll
    for (int o = 16; o > 0; o >>= 1) ss += __shfl_xor_sync(0xffffffffu, ss, o);
    if ((tid & 31) == 0) red[tid >> 5] = ss;
    __syncthreads();
    float tot = red[0];
#pragma unroll
    for (int i = 1; i < 8; i++) tot += red[i];
    float r = rsqrtf(tot * (1.f / (float)E_) + __expf(leps[0]));
    out[(size_t)blockIdx.x * E_ + tid]       = v0 * r;
    out[(size_t)blockIdx.x * E_ + tid + 256] = v1 * r;
}

// ---------------- launch ----------------
extern "C" void kernel_launch(void* const* d_in, const int* in_sizes, int n_in,
                              void* d_out, int out_size)
{
    const float* src      = (const float*)d_in[0];
    const float* pos_emb  = (const float*)d_in[1];
    const float* in_w     = (const float*)d_in[2];
    const float* in_b     = (const float*)d_in[3];
    const float* out_w    = (const float*)d_in[4];
    const float* out_b    = (const float*)d_in[5];
    const float* wpos     = (const float*)d_in[6];
    const float* u        = (const float*)d_in[7];
    const float* v        = (const float*)d_in[8];
    const float* ffm_w1   = (const float*)d_in[9];
    const float* ffm_b1   = (const float*)d_in[10];
    const float* ffm_w2   = (const float*)d_in[11];
    const float* ffm_b2   = (const float*)d_in[12];
    const float* ff_w1    = (const float*)d_in[13];
    const float* ff_b1    = (const float*)d_in[14];
    const float* ff_w2    = (const float*)d_in[15];
    const float* ff_b2    = (const float*)d_in[16];
    const float* pw1_w    = (const float*)d_in[17];
    const float* pw1_b    = (const float*)d_in[18];
    const float* dw_w     = (const float*)d_in[19];
    const float* dw_b     = (const float*)d_in[20];
    const float* pw2_w    = (const float*)d_in[21];
    const float* pw2_b    = (const float*)d_in[22];
    const float* leps     = (const float*)d_in[23];

    float *ff, *x1, *x2, *x3, *qkv, *pp, *sc, *ctx, *glu, *dsw;
    cudaGetSymbolAddress((void**)&ff,  g_ff);
    cudaGetSymbolAddress((void**)&x1,  g_x1);
    cudaGetSymbolAddress((void**)&x2,  g_x2);
    cudaGetSymbolAddress((void**)&x3,  g_x3);
    cudaGetSymbolAddress((void**)&qkv, g_qkv);
    cudaGetSymbolAddress((void**)&pp,  g_pproj);
    cudaGetSymbolAddress((void**)&sc,  g_scores);
    cudaGetSymbolAddress((void**)&ctx, g_ctx);
    cudaGetSymbolAddress((void**)&glu, g_glu);
    cudaGetSymbolAddress((void**)&dsw, g_dsw);

    const size_t smem_scores = (size_t)(3 * 64 * 65 + 64 * 128) * sizeof(float); // 82688 B
    cudaFuncSetAttribute(attn_scores_kernel, cudaFuncAttributeMaxDynamicSharedMemorySize,
                         (int)smem_scores);

    // 1) macaron FFN
    gemm_nt_kernel<EPI_DSWISH><<<dim3(DFF_ / 64, NTOK / 64), 256>>>(
        src, ffm_w1, ffm_b1, nullptr, ff, NTOK, DFF_, E_);
    gemm_nt_kernel<EPI_RES><<<dim3(E_ / 64, NTOK / 64), 256>>>(
        ff, ffm_w2, ffm_b2, src, x1, NTOK, E_, DFF_);

    // 2) attention
    gemm_nt_kernel<EPI_NONE><<<dim3((3 * E_) / 64, NTOK / 64), 256>>>(
        x1, in_w, in_b, nullptr, qkv, NTOK, 3 * E_, E_);
    gemm_nt_kernel<EPI_NONE><<<dim3(E_ / 64, (PLEN + 63) / 64), 256>>>(
        pos_emb, wpos, nullptr, nullptr, pp, PLEN, E_, E_);
    attn_scores_kernel<<<dim3(T_ / 64, T_ / 64, B_ * H_), 256, smem_scores>>>(qkv, pp, u, v, sc);
    softmax_kernel<<<B_ * H_ * T_, 256>>>(sc);
    attn_out_kernel<<<dim3(T_ / 64, B_ * H_), 256>>>(sc, qkv, ctx);
    gemm_nt_kernel<EPI_RES><<<dim3(E_ / 64, NTOK / 64), 256>>>(
        ctx, out_w, out_b, x1, x2, NTOK, E_, E_);

    // 3) conv module
    gemm_nt_kernel<EPI_NONE><<<dim3((2 * E_) / 64, NTOK / 64), 256>>>(
        x2, pw1_w, pw1_b, nullptr, ff, NTOK, 2 * E_, E_);
    glu_kernel<<<(NTOK * E_) / 256, 256>>>(ff, glu);
    dwconv_kernel<<<(NTOK * E_) / 256, 256>>>(glu, dw_w, dw_b, dsw);
    gemm_nt_kernel<EPI_RES><<<dim3(E_ / 64, NTOK / 64), 256>>>(
        dsw, pw2_w, pw2_b, x2, x3, NTOK, E_, E_);

    // 4) second FFN (reuse x1 as x4 output)
    gemm_nt_kernel<EPI_DSWISH><<<dim3(DFF_ / 64, NTOK / 64), 256>>>(
        x3, ff_w1, ff_b1, nullptr, ff, NTOK, DFF_, E_);
    gemm_nt_kernel<EPI_RES><<<dim3(E_ / 64, NTOK / 64), 256>>>(
        ff, ff_w2, ff_b2, x3, x1, NTOK, E_, DFF_);

    // 5) BasicNorm -> output
    basic_norm_kernel<<<NTOK, 256>>>(x1, leps, (float*)d_out);
}

// round 2
// speedup vs baseline: 1.1072x; 1.1072x over previous
#include <cuda_runtime.h>
#include <math.h>
#include <stdint.h>

// ---------------- problem dims ----------------
#define T_    1024
#define B_    4
#define E_    512
#define H_    8
#define D_    64
#define DFF_  2048
#define NTOK  4096            // T_*B_
#define PLEN  2047            // 2T-1
#define KCONV 31

typedef unsigned long long u64;

// ---------------- scratch (device globals; no allocation) ----------------
__device__ float g_ff[NTOK * DFF_];
__device__ float g_x1[NTOK * E_];
__device__ float g_x2[NTOK * E_];
__device__ float g_x3[NTOK * E_];
__device__ float g_qkv[NTOK * 3 * E_];
__device__ float g_pproj[PLEN * E_];
__device__ float g_scores[32ull * T_ * T_];
__device__ float g_ctx[NTOK * E_];
__device__ float g_glu[NTOK * E_];
__device__ float g_dsw[NTOK * E_];

__device__ __forceinline__ float sigmoidf_(float x) { return 1.f / (1.f + __expf(-x)); }

// ---------------- packed f32x2 helpers ----------------
__device__ __forceinline__ u64 pack2_(float lo, float hi) {
    u64 r; asm("mov.b64 %0, {%1, %2};" : "=l"(r) : "f"(lo), "f"(hi)); return r;
}
__device__ __forceinline__ u64 pdup_(float x) {
    u64 r; asm("mov.b64 %0, {%1, %1};" : "=l"(r) : "f"(x)); return r;
}
__device__ __forceinline__ u64 ffma2_(u64 a, u64 b, u64 c) {
    u64 d; asm("fma.rn.f32x2 %0, %1, %2, %3;" : "=l"(d) : "l"(a), "l"(b), "l"(c)); return d;
}
__device__ __forceinline__ float2 unpack2_(u64 v) {
    float2 f; asm("mov.b64 {%0, %1}, %2;" : "=f"(f.x), "=f"(f.y) : "l"(v)); return f;
}

// ---------------- generic NT GEMM: C = epi(A(MxK) * B(NxK)^T + bias) ----------------
// 128x128 tile, 256 threads, 8x8 per thread, BK=16, double-buffered, f32x2 FMA.
enum { EPI_NONE = 0, EPI_DSWISH = 1, EPI_RES = 2 };

template <int EPI>
__global__ void gemm_nt_kernel(const float* __restrict__ A, const float* __restrict__ Bm,
                               const float* __restrict__ bias, const float* __restrict__ res,
                               float* __restrict__ C, int M, int N, int K)
{
    __shared__ float As[2][16][132];   // As[buf][k][m]
    __shared__ float Bs[2][16][132];   // Bs[buf][k][n]
    const int tid = threadIdx.x;
    const int m0 = blockIdx.y * 128, n0 = blockIdx.x * 128;
    const int lr = tid >> 1;            // 0..127: row loaded by this thread
    const int lk = (tid & 1) << 3;      // 0 or 8
    const int tm = (tid >> 4) << 3;     // 0..120
    const int tn = (tid & 15) << 3;

    u64 acc[8][4];
#pragma unroll
    for (int i = 0; i < 8; i++)
#pragma unroll
        for (int j = 0; j < 4; j++) acc[i][j] = 0ull;

    const bool a_ok = (m0 + lr) < M;    // N is always a multiple of 128
    const float* Ap = A + (size_t)(m0 + lr) * K + lk;
    const float* Bp = Bm + (size_t)(n0 + lr) * K + lk;

    float ra[8], rb[8];
    // initial tile load
    {
        float4 z = make_float4(0.f, 0.f, 0.f, 0.f);
        *(float4*)&ra[0] = a_ok ? *(const float4*)(Ap)     : z;
        *(float4*)&ra[4] = a_ok ? *(const float4*)(Ap + 4) : z;
        *(float4*)&rb[0] = *(const float4*)(Bp);
        *(float4*)&rb[4] = *(const float4*)(Bp + 4);
#pragma unroll
        for (int i = 0; i < 8; i++) {
            As[0][lk + i][lr] = ra[i];
            Bs[0][lk + i][lr] = rb[i];
        }
    }
    __syncthreads();

    const int nk = K >> 4;
    for (int kt = 0; kt < nk; kt++) {
        const int buf = kt & 1;
        if (kt + 1 < nk) {
            const float* ap = Ap + ((kt + 1) << 4);
            const float* bp = Bp + ((kt + 1) << 4);
            float4 z = make_float4(0.f, 0.f, 0.f, 0.f);
            *(float4*)&ra[0] = a_ok ? *(const float4*)(ap)     : z;
            *(float4*)&ra[4] = a_ok ? *(const float4*)(ap + 4) : z;
            *(float4*)&rb[0] = *(const float4*)(bp);
            *(float4*)&rb[4] = *(const float4*)(bp + 4);
        }
#pragma unroll
        for (int kk = 0; kk < 16; kk++) {
            const float* as = &As[buf][kk][tm];
            float4 a0 = *(const float4*)as;
            float4 a1 = *(const float4*)(as + 4);
            const ulonglong2* bp2 = (const ulonglong2*)&Bs[buf][kk][tn];
            ulonglong2 bq0 = bp2[0], bq1 = bp2[1];
            u64 b0 = bq0.x, b1 = bq0.y, b2 = bq1.x, b3 = bq1.y;
            u64 ad[8];
            ad[0] = pdup_(a0.x); ad[1] = pdup_(a0.y); ad[2] = pdup_(a0.z); ad[3] = pdup_(a0.w);
            ad[4] = pdup_(a1.x); ad[5] = pdup_(a1.y); ad[6] = pdup_(a1.z); ad[7] = pdup_(a1.w);
#pragma unroll
            for (int i = 0; i < 8; i++) {
                acc[i][0] = ffma2_(ad[i], b0, acc[i][0]);
                acc[i][1] = ffma2_(ad[i], b1, acc[i][1]);
                acc[i][2] = ffma2_(ad[i], b2, acc[i][2]);
                acc[i][3] = ffma2_(ad[i], b3, acc[i][3]);
            }
        }
        if (kt + 1 < nk) {
            const int nb = buf ^ 1;
#pragma unroll
            for (int i = 0; i < 8; i++) {
                As[nb][lk + i][lr] = ra[i];
                Bs[nb][lk + i][lr] = rb[i];
            }
            __syncthreads();
        }
    }

    // epilogue
#pragma unroll
    for (int i = 0; i < 8; i++) {
        int gm = m0 + tm + i;
        if (gm >= M) continue;
        float o[8];
#pragma unroll
        for (int j = 0; j < 4; j++) {
            float2 t = unpack2_(acc[i][j]);
            o[2 * j] = t.x; o[2 * j + 1] = t.y;
        }
        size_t off = (size_t)gm * N + n0 + tn;
#pragma unroll
        for (int j = 0; j < 8; j++) {
            float v = o[j];
            if (bias) v += bias[n0 + tn + j];
            if (EPI == EPI_DSWISH) v = v * sigmoidf_(v - 1.f);
            if (EPI == EPI_RES)    v += res[off + j];
            o[j] = v;
        }
        *(float4*)&C[off]     = *(float4*)&o[0];
        *(float4*)&C[off + 4] = *(float4*)&o[4];
    }
}

// ---------------- attention scores: scores = (q+u)K^T + rel_shift((q+v)P) ----------------
__global__ void attn_scores_kernel(const float* __restrict__ qkv,
                                   const float* __restrict__ pproj,
                                   const float* __restrict__ u,
                                   const float* __restrict__ v,
                                   float* __restrict__ scores)
{
    extern __shared__ float sm[];
    float* Qu = sm;                 // [64][65]
    float* Qv = Qu + 64 * 65;       // [64][65]
    float* Kt = Qv + 64 * 65;       // [64][65]
    float* Ps = Kt + 64 * 65;       // [64][128]

    const int bh = blockIdx.z;
    const int b = bh >> 3, h = bh & 7;
    const int i0 = blockIdx.y * 64, j0 = blockIdx.x * 64;
    const int tid = threadIdx.x;
    const float scale = 0.125f;

    for (int idx = tid; idx < 64 * 64; idx += 256) {
        int li = idx >> 6, d = idx & 63;
        float q = qkv[(size_t)((i0 + li) * B_ + b) * (3 * E_) + h * 64 + d] * scale;
        Qu[li * 65 + d] = q + u[h * 64 + d];
        Qv[li * 65 + d] = q + v[h * 64 + d];
        Kt[li * 65 + d] = qkv[(size_t)((j0 + li) * B_ + b) * (3 * E_) + E_ + h * 64 + d];
    }
    const int m_min = (T_ - 1) - (i0 + 63) + j0;
    for (int idx = tid; idx < 64 * 127; idx += 256) {
        int d = idx / 127, mm = idx % 127;
        Ps[d * 128 + mm] = pproj[(size_t)(m_min + mm) * E_ + h * 64 + d];
    }
    __syncthreads();

    const int tm = (tid >> 4) << 2;
    const int tn = (tid & 15) << 2;
    const int base = 63 - tm + tn;
    u64 acc2[4][2];
#pragma unroll
    for (int i = 0; i < 4; i++) { acc2[i][0] = 0ull; acc2[i][1] = 0ull; }

#pragma unroll 4
    for (int d = 0; d < 64; d++) {
        u64 ad[4], cd[4];
#pragma unroll
        for (int ii = 0; ii < 4; ii++) {
            ad[ii] = pdup_(Qu[(tm + ii) * 65 + d]);
            cd[ii] = pdup_(Qv[(tm + ii) * 65 + d]);
        }
        float bb0 = Kt[(tn + 0) * 65 + d], bb1 = Kt[(tn + 1) * 65 + d];
        float bb2 = Kt[(tn + 2) * 65 + d], bb3 = Kt[(tn + 3) * 65 + d];
        u64 kb0 = pack2_(bb0, bb1), kb1 = pack2_(bb2, bb3);
        float p7[7];
#pragma unroll
        for (int t = 0; t < 7; t++) p7[t] = Ps[d * 128 + base + t - 3];
        u64 pp[6];
#pragma unroll
        for (int t = 0; t < 6; t++) pp[t] = pack2_(p7[t], p7[t + 1]);
#pragma unroll
        for (int ii = 0; ii < 4; ii++) {
            acc2[ii][0] = ffma2_(ad[ii], kb0, acc2[ii][0]);
            acc2[ii][1] = ffma2_(ad[ii], kb1, acc2[ii][1]);
            acc2[ii][0] = ffma2_(cd[ii], pp[3 - ii], acc2[ii][0]);
            acc2[ii][1] = ffma2_(cd[ii], pp[5 - ii], acc2[ii][1]);
        }
    }

    const size_t ob = ((size_t)bh * T_ + i0) * T_ + j0;
#pragma unroll
    for (int ii = 0; ii < 4; ii++) {
        float2 t0 = unpack2_(acc2[ii][0]);
        float2 t1 = unpack2_(acc2[ii][1]);
        float4 o = make_float4(t0.x, t0.y, t1.x, t1.y);
        *(float4*)&scores[ob + (size_t)(tm + ii) * T_ + tn] = o;
    }
}

// ---------------- softmax over rows of length 1024 (in place) ----------------
__global__ void softmax_kernel(float* __restrict__ s)
{
    __shared__ float red[8];
    __shared__ float red2[8];
    const int tid = threadIdx.x;
    float* p = s + (size_t)blockIdx.x * 1024;
    float v[4];
    float m = -1e30f;
#pragma unroll
    for (int i = 0; i < 4; i++) { v[i] = p[tid + i * 256]; m = fmaxf(m, v[i]); }
#pragma unroll
    for (int o = 16; o > 0; o >>= 1) m = fmaxf(m, __shfl_xor_sync(0xffffffffu, m, o));
    if ((tid & 31) == 0) red[tid >> 5] = m;
    __syncthreads();
    m = red[0];
#pragma unroll
    for (int i = 1; i < 8; i++) m = fmaxf(m, red[i]);

    float sum = 0.f;
#pragma unroll
    for (int i = 0; i < 4; i++) { v[i] = __expf(v[i] - m); sum += v[i]; }
#pragma unroll
    for (int o = 16; o > 0; o >>= 1) sum += __shfl_xor_sync(0xffffffffu, sum, o);
    if ((tid & 31) == 0) red2[tid >> 5] = sum;
    __syncthreads();
    sum = red2[0];
#pragma unroll
    for (int i = 1; i < 8; i++) sum += red2[i];
    float inv = 1.f / sum;
#pragma unroll
    for (int i = 0; i < 4; i++) p[tid + i * 256] = v[i] * inv;
}

// ---------------- attn @ V -> ctx in (T,B,E) layout ----------------
__global__ void attn_out_kernel(const float* __restrict__ scores,
                                const float* __restrict__ qkv,
                                float* __restrict__ ctx)
{
    __shared__ float As[64][33];
    __shared__ float Bs[32][68];
    const int bh = blockIdx.y;
    const int b = bh >> 3, h = bh & 7;
    const int i0 = blockIdx.x * 64;
    const int tid = threadIdx.x;
    const float* S = scores + ((size_t)bh * T_ + i0) * T_;
    const int tm = (tid >> 4) << 2;
    const int tn = (tid & 15) << 2;
    u64 acc[4][2];
#pragma unroll
    for (int i = 0; i < 4; i++) { acc[i][0] = 0ull; acc[i][1] = 0ull; }

    for (int k0 = 0; k0 < T_; k0 += 32) {
#pragma unroll
        for (int r = 0; r < 8; r++) {
            int idx = tid + r * 256;
            int ii = idx >> 5, kk = idx & 31;
            As[ii][kk] = S[(size_t)ii * T_ + k0 + kk];
        }
#pragma unroll
        for (int r = 0; r < 8; r++) {
            int idx = tid + r * 256;
            int kk = idx >> 6, d = idx & 63;
            Bs[kk][d] = qkv[(size_t)((k0 + kk) * B_ + b) * (3 * E_) + 2 * E_ + h * 64 + d];
        }
        __syncthreads();
#pragma unroll
        for (int kk = 0; kk < 32; kk++) {
            const ulonglong2* bp2 = (const ulonglong2*)&Bs[kk][tn];
            ulonglong2 bq = bp2[0];
#pragma unroll
            for (int x = 0; x < 4; x++) {
                u64 a = pdup_(As[tm + x][kk]);
                acc[x][0] = ffma2_(a, bq.x, acc[x][0]);
                acc[x][1] = ffma2_(a, bq.y, acc[x][1]);
            }
        }
        __syncthreads();
    }
#pragma unroll
    for (int x = 0; x < 4; x++) {
        int gi = i0 + tm + x;
        float2 t0 = unpack2_(acc[x][0]);
        float2 t1 = unpack2_(acc[x][1]);
        float4 o = make_float4(t0.x, t0.y, t1.x, t1.y);
        *(float4*)&ctx[(size_t)(gi * B_ + b) * E_ + h * 64 + tn] = o;
    }
}

// ---------------- GLU over channel dim ----------------
__global__ void glu_kernel(const float* __restrict__ y, float* __restrict__ out)
{
    int idx = blockIdx.x * 256 + threadIdx.x;
    if (idx >= NTOK * E_) return;
    int r = idx >> 9, c = idx & 511;
    float a = y[(size_t)r * 1024 + c];
    float g = y[(size_t)r * 1024 + 512 + c];
    out[idx] = a * sigmoidf_(g);
}

// ---------------- depthwise conv (K=31, pad=15) + DoubleSwish ----------------
__global__ void dwconv_kernel(const float* __restrict__ x, const float* __restrict__ w,
                              const float* __restrict__ bias, float* __restrict__ out)
{
    int idx = blockIdx.x * 256 + threadIdx.x;
    if (idx >= NTOK * E_) return;
    int c = idx & 511;
    int tb = idx >> 9;
    int t = tb >> 2, b = tb & 3;
    float acc = bias[c];
#pragma unroll
    for (int k = 0; k < KCONV; k++) {
        int tt = t + k - 15;
        if (tt >= 0 && tt < T_)
            acc += x[(size_t)(tt * B_ + b) * E_ + c] * w[c * KCONV + k];
    }
    out[idx] = acc * sigmoidf_(acc - 1.f);
}

// ---------------- BasicNorm ----------------
__global__ void basic_norm_kernel(const float* __restrict__ x, const float* __restrict__ leps,
                                  float* __restrict__ out)
{
    __shared__ float red[8];
    const int tid = threadIdx.x;
    const float* p = x + (size_t)blockIdx.x * E_;
    float v0 = p[tid], v1 = p[tid + 256];
    float ss = v0 * v0 + v1 * v1;
#pragma unroll
    for (int o = 16; o > 0; o >>= 1) ss += __shfl_xor_sync(0xffffffffu, ss, o);
    if ((tid & 31) == 0) red[tid >> 5] = ss;
    __syncthreads();
    float tot = red[0];
#pragma unroll
    for (int i = 1; i < 8; i++) tot += red[i];
    float r = rsqrtf(tot * (1.f / (float)E_) + __expf(leps[0]));
    out[(size_t)blockIdx.x * E_ + tid]       = v0 * r;
    out[(size_t)blockIdx.x * E_ + tid + 256] = v1 * r;
}

// ---------------- launch ----------------
extern "C" void kernel_launch(void* const* d_in, const int* in_sizes, int n_in,
                              void* d_out, int out_size)
{
    const float* src      = (const float*)d_in[0];
    const float* pos_emb  = (const float*)d_in[1];
    const float* in_w     = (const float*)d_in[2];
    const float* in_b     = (const float*)d_in[3];
    const float* out_w    = (const float*)d_in[4];
    const float* out_b    = (const float*)d_in[5];
    const float* wpos     = (const float*)d_in[6];
    const float* u        = (const float*)d_in[7];
    const float* v        = (const float*)d_in[8];
    const float* ffm_w1   = (const float*)d_in[9];
    const float* ffm_b1   = (const float*)d_in[10];
    const float* ffm_w2   = (const float*)d_in[11];
    const float* ffm_b2   = (const float*)d_in[12];
    const float* ff_w1    = (const float*)d_in[13];
    const float* ff_b1    = (const float*)d_in[14];
    const float* ff_w2    = (const float*)d_in[15];
    const float* ff_b2    = (const float*)d_in[16];
    const float* pw1_w    = (const float*)d_in[17];
    const float* pw1_b    = (const float*)d_in[18];
    const float* dw_w     = (const float*)d_in[19];
    const float* dw_b     = (const float*)d_in[20];
    const float* pw2_w    = (const float*)d_in[21];
    const float* pw2_b    = (const float*)d_in[22];
    const float* leps     = (const float*)d_in[23];

    float *ff, *x1, *x2, *x3, *qkv, *pp, *sc, *ctx, *glu, *dsw;
    cudaGetSymbolAddress((void**)&ff,  g_ff);
    cudaGetSymbolAddress((void**)&x1,  g_x1);
    cudaGetSymbolAddress((void**)&x2,  g_x2);
    cudaGetSymbolAddress((void**)&x3,  g_x3);
    cudaGetSymbolAddress((void**)&qkv, g_qkv);
    cudaGetSymbolAddress((void**)&pp,  g_pproj);
    cudaGetSymbolAddress((void**)&sc,  g_scores);
    cudaGetSymbolAddress((void**)&ctx, g_ctx);
    cudaGetSymbolAddress((void**)&glu, g_glu);
    cudaGetSymbolAddress((void**)&dsw, g_dsw);

    const size_t smem_scores = (size_t)(3 * 64 * 65 + 64 * 128) * sizeof(float);
    cudaFuncSetAttribute(attn_scores_kernel, cudaFuncAttributeMaxDynamicSharedMemorySize,
                         (int)smem_scores);

    // 1) macaron FFN
    gemm_nt_kernel<EPI_DSWISH><<<dim3(DFF_ / 128, NTOK / 128), 256>>>(
        src, ffm_w1, ffm_b1, nullptr, ff, NTOK, DFF_, E_);
    gemm_nt_kernel<EPI_RES><<<dim3(E_ / 128, NTOK / 128), 256>>>(
        ff, ffm_w2, ffm_b2, src, x1, NTOK, E_, DFF_);

    // 2) attention
    gemm_nt_kernel<EPI_NONE><<<dim3((3 * E_) / 128, NTOK / 128), 256>>>(
        x1, in_w, in_b, nullptr, qkv, NTOK, 3 * E_, E_);
    gemm_nt_kernel<EPI_NONE><<<dim3(E_ / 128, (PLEN + 127) / 128), 256>>>(
        pos_emb, wpos, nullptr, nullptr, pp, PLEN, E_, E_);
    attn_scores_kernel<<<dim3(T_ / 64, T_ / 64, B_ * H_), 256, smem_scores>>>(qkv, pp, u, v, sc);
    softmax_kernel<<<B_ * H_ * T_, 256>>>(sc);
    attn_out_kernel<<<dim3(T_ / 64, B_ * H_), 256>>>(sc, qkv, ctx);
    gemm_nt_kernel<EPI_RES><<<dim3(E_ / 128, NTOK / 128), 256>>>(
        ctx, out_w, out_b, x1, x2, NTOK, E_, E_);

    // 3) conv module
    gemm_nt_kernel<EPI_NONE><<<dim3((2 * E_) / 128, NTOK / 128), 256>>>(
        x2, pw1_w, pw1_b, nullptr, ff, NTOK, 2 * E_, E_);
    glu_kernel<<<(NTOK * E_) / 256, 256>>>(ff, glu);
    dwconv_kernel<<<(NTOK * E_) / 256, 256>>>(glu, dw_w, dw_b, dsw);
    gemm_nt_kernel<EPI_RES><<<dim3(E_ / 128, NTOK / 128), 256>>>(
        dsw, pw2_w, pw2_b, x2, x3, NTOK, E_, E_);

    // 4) second FFN
    gemm_nt_kernel<EPI_DSWISH><<<dim3(DFF_ / 128, NTOK / 128), 256>>>(
        x3, ff_w1, ff_b1, nullptr, ff, NTOK, DFF_, E_);
    gemm_nt_kernel<EPI_RES><<<dim3(E_ / 128, NTOK / 128), 256>>>(
        ff, ff_w2, ff_b2, x3, x1, NTOK, E_, DFF_);

    // 5) BasicNorm -> output
    basic_norm_kernel<<<NTOK, 256>>>(x1, leps, (float*)d_out);
}

// round 3
// speedup vs baseline: 1.2315x; 1.1123x over previous
#include <cuda_runtime.h>
#include <math.h>
#include <stdint.h>

// ---------------- problem dims ----------------
#define T_    1024
#define B_    4
#define E_    512
#define H_    8
#define D_    64
#define DFF_  2048
#define NTOK  4096
#define PLEN  2047
#define KCONV 31

typedef unsigned long long u64;

// ---------------- scratch (device globals; no allocation) ----------------
__device__ float g_ff[NTOK * DFF_];
__device__ float g_x1[NTOK * E_];
__device__ float g_x2[NTOK * E_];
__device__ float g_x3[NTOK * E_];
__device__ float g_qkv[NTOK * 3 * E_];
__device__ float g_pproj[PLEN * E_];
__device__ float g_scores[32ull * T_ * T_];
__device__ float g_ctx[NTOK * E_];
__device__ float g_glu[NTOK * E_];
__device__ float g_dsw[NTOK * E_];
__device__ float g_wT[6291456];         // transposed weights, 24 MB

// transposed-weight offsets (floats)
#define OFF_FFM_W1T 0
#define OFF_FFM_W2T 1048576
#define OFF_IN_WT   2097152
#define OFF_WPOST   2883584
#define OFF_OUT_WT  3145728
#define OFF_PW1_WT  3407872
#define OFF_PW2_WT  3932160
#define OFF_FF_W1T  4194304
#define OFF_FF_W2T  5242880

__device__ __forceinline__ float sigmoidf_(float x) { return 1.f / (1.f + __expf(-x)); }

// ---------------- packed f32x2 helpers ----------------
__device__ __forceinline__ u64 pack2_(float lo, float hi) {
    u64 r; asm("mov.b64 %0, {%1, %2};" : "=l"(r) : "f"(lo), "f"(hi)); return r;
}
__device__ __forceinline__ u64 pdup_(float x) {
    u64 r; asm("mov.b64 %0, {%1, %1};" : "=l"(r) : "f"(x)); return r;
}
__device__ __forceinline__ u64 ffma2_(u64 a, u64 b, u64 c) {
    u64 d; asm("fma.rn.f32x2 %0, %1, %2, %3;" : "=l"(d) : "l"(a), "l"(b), "l"(c)); return d;
}
__device__ __forceinline__ float2 unpack2_(u64 v) {
    float2 f; asm("mov.b64 {%0, %1}, %2;" : "=f"(f.x), "=f"(f.y) : "l"(v)); return f;
}
__device__ __forceinline__ uint32_t smem_u32_(const void* p) {
    return (uint32_t)__cvta_generic_to_shared(p);
}
__device__ __forceinline__ void cpasync16_(uint32_t dst, const float* src, int srcbytes) {
    asm volatile("cp.async.ca.shared.global [%0], [%1], 16, %2;"
                 :: "r"(dst), "l"(src), "r"(srcbytes));
}

// ---------------- weight transpose: out[c][r] = in[r][c] ----------------
__global__ void transpose_kernel(const float* __restrict__ in, float* __restrict__ out,
                                 int R, int C)
{
    __shared__ float t[32][33];
    int c0 = blockIdx.x * 32, r0 = blockIdx.y * 32;
    int x = threadIdx.x, y = threadIdx.y;        // 32 x 8
#pragma unroll
    for (int i = 0; i < 32; i += 8) {
        int r = r0 + y + i, c = c0 + x;
        t[y + i][x] = (r < R && c < C) ? in[(size_t)r * C + c] : 0.f;
    }
    __syncthreads();
#pragma unroll
    for (int i = 0; i < 32; i += 8) {
        int r = c0 + y + i, c = r0 + x;
        if (r < C && c < R) out[(size_t)r * R + c] = t[x][y + i];
    }
}

// ---------------- NN GEMM: C = epi(A(MxK) * Bt(KxN) + bias) ----------------
// 128x128 tile, 256 threads, 8x8/thread, 4-stage cp.async pipeline, f32x2 FMA.
enum { EPI_NONE = 0, EPI_DSWISH = 1, EPI_RES = 2 };
#define GSTAGES 4
#define GEMM_SMEM (GSTAGES * (128 * 16 + 16 * 128) * 4)   // 65536 B

template <int EPI>
__global__ void __launch_bounds__(256, 2)
gemm_nn_kernel(const float* __restrict__ A, const float* __restrict__ Bt,
               const float* __restrict__ bias, const float* __restrict__ res,
               float* __restrict__ C, int M, int N, int K)
{
    extern __shared__ float smem_[];
    float* As = smem_;                         // [GSTAGES][128][16]
    float* Bs = smem_ + GSTAGES * 128 * 16;    // [GSTAGES][16][128]

    const int tid = threadIdx.x;
    const int m0 = blockIdx.y * 128, n0 = blockIdx.x * 128;
    const int tm = (tid >> 4) << 3;
    const int tn = (tid & 15) << 3;
    const int nk = K >> 4;

    // load mapping (2 x 16B chunks each for A and B per thread)
    const int ar0 = tid >> 2,        ac0 = (tid & 3) << 2;          // chunk tid
    const int ar1 = (tid + 256) >> 2, ac1 = ((tid + 256) & 3) << 2; // chunk tid+256
    const int bk0 = tid >> 5,        bn0 = (tid & 31) << 2;
    const int bk1 = (tid + 256) >> 5, bn1 = ((tid + 256) & 31) << 2;
    const int asz0 = (m0 + ar0) < M ? 16 : 0;
    const int asz1 = (m0 + ar1) < M ? 16 : 0;
    const float* Ap0 = A + (size_t)((m0 + ar0) < M ? (m0 + ar0) : 0) * K + ac0;
    const float* Ap1 = A + (size_t)((m0 + ar1) < M ? (m0 + ar1) : 0) * K + ac1;
    const float* Bp0 = Bt + (size_t)bk0 * N + n0 + bn0;
    const float* Bp1 = Bt + (size_t)bk1 * N + n0 + bn1;

    const uint32_t As_u = smem_u32_(As);
    const uint32_t Bs_u = smem_u32_(Bs);
    const uint32_t adst0 = As_u + (ar0 * 16 + ac0) * 4;
    const uint32_t adst1 = As_u + (ar1 * 16 + ac1) * 4;
    const uint32_t bdst0 = Bs_u + (bk0 * 128 + bn0) * 4;
    const uint32_t bdst1 = Bs_u + (bk1 * 128 + bn1) * 4;

    u64 acc[8][4];
#pragma unroll
    for (int i = 0; i < 8; i++)
#pragma unroll
        for (int j = 0; j < 4; j++) acc[i][j] = 0ull;

    // prologue: stages 0..2
#pragma unroll
    for (int kt = 0; kt < 3; kt++) {
        if (kt < nk) {
            uint32_t so = kt * 2048 * 4;       // stage offset bytes (A and B both 2048 floats)
            cpasync16_(adst0 + so, Ap0 + kt * 16, asz0);
            cpasync16_(adst1 + so, Ap1 + kt * 16, asz1);
            cpasync16_(bdst0 + so, Bp0 + (size_t)kt * 16 * N, 16);
            cpasync16_(bdst1 + so, Bp1 + (size_t)kt * 16 * N, 16);
        }
        asm volatile("cp.async.commit_group;");
    }

    for (int kt = 0; kt < nk; kt++) {
        asm volatile("cp.async.wait_group 2;");
        __syncthreads();
        const int buf = kt & 3;
        const float* as = As + buf * 2048 + tm * 16;
        const float* bs = Bs + buf * 2048;
#pragma unroll
        for (int kk = 0; kk < 16; kk++) {
            const ulonglong2* bp2 = (const ulonglong2*)(bs + kk * 128 + tn);
            ulonglong2 bq0 = bp2[0], bq1 = bp2[1];
            u64 ad[8];
#pragma unroll
            for (int i = 0; i < 8; i++) ad[i] = pdup_(as[i * 16 + kk]);
#pragma unroll
            for (int i = 0; i < 8; i++) {
                acc[i][0] = ffma2_(ad[i], bq0.x, acc[i][0]);
                acc[i][1] = ffma2_(ad[i], bq0.y, acc[i][1]);
                acc[i][2] = ffma2_(ad[i], bq1.x, acc[i][2]);
                acc[i][3] = ffma2_(ad[i], bq1.y, acc[i][3]);
            }
        }
        const int ktn = kt + 3;
        if (ktn < nk) {
            uint32_t so = (ktn & 3) * 2048 * 4;
            cpasync16_(adst0 + so, Ap0 + ktn * 16, asz0);
            cpasync16_(adst1 + so, Ap1 + ktn * 16, asz1);
            cpasync16_(bdst0 + so, Bp0 + (size_t)ktn * 16 * N, 16);
            cpasync16_(bdst1 + so, Bp1 + (size_t)ktn * 16 * N, 16);
        }
        asm volatile("cp.async.commit_group;");
        if (kt + 1 < nk) __syncthreads();
    }

    // epilogue
#pragma unroll
    for (int i = 0; i < 8; i++) {
        int gm = m0 + tm + i;
        if (gm >= M) continue;
        float o[8];
#pragma unroll
        for (int j = 0; j < 4; j++) {
            float2 t = unpack2_(acc[i][j]);
            o[2 * j] = t.x; o[2 * j + 1] = t.y;
        }
        size_t off = (size_t)gm * N + n0 + tn;
#pragma unroll
        for (int j = 0; j < 8; j++) {
            float v = o[j];
            if (bias) v += bias[n0 + tn + j];
            if (EPI == EPI_DSWISH) v = v * sigmoidf_(v - 1.f);
            if (EPI == EPI_RES)    v += res[off + j];
            o[j] = v;
        }
        *(float4*)&C[off]     = *(float4*)&o[0];
        *(float4*)&C[off + 4] = *(float4*)&o[4];
    }
}

// ---------------- attention scores: scores = (q+u)K^T + rel_shift((q+v)P) ----------------
__global__ void attn_scores_kernel(const float* __restrict__ qkv,
                                   const float* __restrict__ pproj,
                                   const float* __restrict__ u,
                                   const float* __restrict__ v,
                                   float* __restrict__ scores)
{
    extern __shared__ float sm[];
    float* Qu = sm;
    float* Qv = Qu + 64 * 65;
    float* Kt = Qv + 64 * 65;
    float* Ps = Kt + 64 * 65;

    const int bh = blockIdx.z;
    const int b = bh >> 3, h = bh & 7;
    const int i0 = blockIdx.y * 64, j0 = blockIdx.x * 64;
    const int tid = threadIdx.x;
    const float scale = 0.125f;

    for (int idx = tid; idx < 64 * 64; idx += 256) {
        int li = idx >> 6, d = idx & 63;
        float q = qkv[(size_t)((i0 + li) * B_ + b) * (3 * E_) + h * 64 + d] * scale;
        Qu[li * 65 + d] = q + u[h * 64 + d];
        Qv[li * 65 + d] = q + v[h * 64 + d];
        Kt[li * 65 + d] = qkv[(size_t)((j0 + li) * B_ + b) * (3 * E_) + E_ + h * 64 + d];
    }
    const int m_min = (T_ - 1) - (i0 + 63) + j0;
    for (int idx = tid; idx < 64 * 127; idx += 256) {
        int d = idx / 127, mm = idx % 127;
        Ps[d * 128 + mm] = pproj[(size_t)(m_min + mm) * E_ + h * 64 + d];
    }
    __syncthreads();

    const int tm = (tid >> 4) << 2;
    const int tn = (tid & 15) << 2;
    const int base = 63 - tm + tn;
    u64 acc2[4][2];
#pragma unroll
    for (int i = 0; i < 4; i++) { acc2[i][0] = 0ull; acc2[i][1] = 0ull; }

#pragma unroll 4
    for (int d = 0; d < 64; d++) {
        u64 ad[4], cd[4];
#pragma unroll
        for (int ii = 0; ii < 4; ii++) {
            ad[ii] = pdup_(Qu[(tm + ii) * 65 + d]);
            cd[ii] = pdup_(Qv[(tm + ii) * 65 + d]);
        }
        float bb0 = Kt[(tn + 0) * 65 + d], bb1 = Kt[(tn + 1) * 65 + d];
        float bb2 = Kt[(tn + 2) * 65 + d], bb3 = Kt[(tn + 3) * 65 + d];
        u64 kb0 = pack2_(bb0, bb1), kb1 = pack2_(bb2, bb3);
        float p7[7];
#pragma unroll
        for (int t = 0; t < 7; t++) p7[t] = Ps[d * 128 + base + t - 3];
        u64 pp[6];
#pragma unroll
        for (int t = 0; t < 6; t++) pp[t] = pack2_(p7[t], p7[t + 1]);
#pragma unroll
        for (int ii = 0; ii < 4; ii++) {
            acc2[ii][0] = ffma2_(ad[ii], kb0, acc2[ii][0]);
            acc2[ii][1] = ffma2_(ad[ii], kb1, acc2[ii][1]);
            acc2[ii][0] = ffma2_(cd[ii], pp[3 - ii], acc2[ii][0]);
            acc2[ii][1] = ffma2_(cd[ii], pp[5 - ii], acc2[ii][1]);
        }
    }

    const size_t ob = ((size_t)bh * T_ + i0) * T_ + j0;
#pragma unroll
    for (int ii = 0; ii < 4; ii++) {
        float2 t0 = unpack2_(acc2[ii][0]);
        float2 t1 = unpack2_(acc2[ii][1]);
        float4 o = make_float4(t0.x, t0.y, t1.x, t1.y);
        *(float4*)&scores[ob + (size_t)(tm + ii) * T_ + tn] = o;
    }
}

// ---------------- softmax over rows of length 1024 (in place) ----------------
__global__ void softmax_kernel(float* __restrict__ s)
{
    __shared__ float red[8];
    __shared__ float red2[8];
    const int tid = threadIdx.x;
    float* p = s + (size_t)blockIdx.x * 1024;
    float v[4];
    float m = -1e30f;
#pragma unroll
    for (int i = 0; i < 4; i++) { v[i] = p[tid + i * 256]; m = fmaxf(m, v[i]); }
#pragma unroll
    for (int o = 16; o > 0; o >>= 1) m = fmaxf(m, __shfl_xor_sync(0xffffffffu, m, o));
    if ((tid & 31) == 0) red[tid >> 5] = m;
    __syncthreads();
    m = red[0];
#pragma unroll
    for (int i = 1; i < 8; i++) m = fmaxf(m, red[i]);

    float sum = 0.f;
#pragma unroll
    for (int i = 0; i < 4; i++) { v[i] = __expf(v[i] - m); sum += v[i]; }
#pragma unroll
    for (int o = 16; o > 0; o >>= 1) sum += __shfl_xor_sync(0xffffffffu, sum, o);
    if ((tid & 31) == 0) red2[tid >> 5] = sum;
    __syncthreads();
    sum = red2[0];
#pragma unroll
    for (int i = 1; i < 8; i++) sum += red2[i];
    float inv = 1.f / sum;
#pragma unroll
    for (int i = 0; i < 4; i++) p[tid + i * 256] = v[i] * inv;
}

// ---------------- attn @ V -> ctx in (T,B,E) layout ----------------
__global__ void attn_out_kernel(const float* __restrict__ scores,
                                const float* __restrict__ qkv,
                                float* __restrict__ ctx)
{
    __shared__ float As[64][33];
    __shared__ float Bs[32][68];
    const int bh = blockIdx.y;
    const int b = bh >> 3, h = bh & 7;
    const int i0 = blockIdx.x * 64;
    const int tid = threadIdx.x;
    const float* S = scores + ((size_t)bh * T_ + i0) * T_;
    const int tm = (tid >> 4) << 2;
    const int tn = (tid & 15) << 2;
    u64 acc[4][2];
#pragma unroll
    for (int i = 0; i < 4; i++) { acc[i][0] = 0ull; acc[i][1] = 0ull; }

    for (int k0 = 0; k0 < T_; k0 += 32) {
#pragma unroll
        for (int r = 0; r < 8; r++) {
            int idx = tid + r * 256;
            int ii = idx >> 5, kk = idx & 31;
            As[ii][kk] = S[(size_t)ii * T_ + k0 + kk];
        }
#pragma unroll
        for (int r = 0; r < 8; r++) {
            int idx = tid + r * 256;
            int kk = idx >> 6, d = idx & 63;
            Bs[kk][d] = qkv[(size_t)((k0 + kk) * B_ + b) * (3 * E_) + 2 * E_ + h * 64 + d];
        }
        __syncthreads();
#pragma unroll
        for (int kk = 0; kk < 32; kk++) {
            const ulonglong2* bp2 = (const ulonglong2*)&Bs[kk][tn];
            ulonglong2 bq = bp2[0];
#pragma unroll
            for (int x = 0; x < 4; x++) {
                u64 a = pdup_(As[tm + x][kk]);
                acc[x][0] = ffma2_(a, bq.x, acc[x][0]);
                acc[x][1] = ffma2_(a, bq.y, acc[x][1]);
            }
        }
        __syncthreads();
    }
#pragma unroll
    for (int x = 0; x < 4; x++) {
        int gi = i0 + tm + x;
        float2 t0 = unpack2_(acc[x][0]);
        float2 t1 = unpack2_(acc[x][1]);
        float4 o = make_float4(t0.x, t0.y, t1.x, t1.y);
        *(float4*)&ctx[(size_t)(gi * B_ + b) * E_ + h * 64 + tn] = o;
    }
}

// ---------------- GLU ----------------
__global__ void glu_kernel(const float* __restrict__ y, float* __restrict__ out)
{
    int idx = blockIdx.x * 256 + threadIdx.x;
    if (idx >= NTOK * E_) return;
    int r = idx >> 9, c = idx & 511;
    float a = y[(size_t)r * 1024 + c];
    float g = y[(size_t)r * 1024 + 512 + c];
    out[idx] = a * sigmoidf_(g);
}

// ---------------- depthwise conv (K=31, pad=15) + DoubleSwish ----------------
__global__ void dwconv_kernel(const float* __restrict__ x, const float* __restrict__ w,
                              const float* __restrict__ bias, float* __restrict__ out)
{
    int idx = blockIdx.x * 256 + threadIdx.x;
    if (idx >= NTOK * E_) return;
    int c = idx & 511;
    int tb = idx >> 9;
    int t = tb >> 2, b = tb & 3;
    float acc = bias[c];
#pragma unroll
    for (int k = 0; k < KCONV; k++) {
        int tt = t + k - 15;
        if (tt >= 0 && tt < T_)
            acc += x[(size_t)(tt * B_ + b) * E_ + c] * w[c * KCONV + k];
    }
    out[idx] = acc * sigmoidf_(acc - 1.f);
}

// ---------------- BasicNorm ----------------
__global__ void basic_norm_kernel(const float* __restrict__ x, const float* __restrict__ leps,
                                  float* __restrict__ out)
{
    __shared__ float red[8];
    const int tid = threadIdx.x;
    const float* p = x + (size_t)blockIdx.x * E_;
    float v0 = p[tid], v1 = p[tid + 256];
    float ss = v0 * v0 + v1 * v1;
#pragma unroll
    for (int o = 16; o > 0; o >>= 1) ss += __shfl_xor_sync(0xffffffffu, ss, o);
    if ((tid & 31) == 0) red[tid >> 5] = ss;
    __syncthreads();
    float tot = red[0];
#pragma unroll
    for (int i = 1; i < 8; i++) tot += red[i];
    float r = rsqrtf(tot * (1.f / (float)E_) + __expf(leps[0]));
    out[(size_t)blockIdx.x * E_ + tid]       = v0 * r;
    out[(size_t)blockIdx.x * E_ + tid + 256] = v1 * r;
}

// ---------------- launch ----------------
extern "C" void kernel_launch(void* const* d_in, const int* in_sizes, int n_in,
                              void* d_out, int out_size)
{
    const float* src      = (const float*)d_in[0];
    const float* pos_emb  = (const float*)d_in[1];
    const float* in_w     = (const float*)d_in[2];
    const float* in_b     = (const float*)d_in[3];
    const float* out_w    = (const float*)d_in[4];
    const float* out_b    = (const float*)d_in[5];
    const float* wpos     = (const float*)d_in[6];
    const float* u        = (const float*)d_in[7];
    const float* v        = (const float*)d_in[8];
    const float* ffm_w1   = (const float*)d_in[9];
    const float* ffm_b1   = (const float*)d_in[10];
    const float* ffm_w2   = (const float*)d_in[11];
    const float* ffm_b2   = (const float*)d_in[12];
    const float* ff_w1    = (const float*)d_in[13];
    const float* ff_b1    = (const float*)d_in[14];
    const float* ff_w2    = (const float*)d_in[15];
    const float* ff_b2    = (const float*)d_in[16];
    const float* pw1_w    = (const float*)d_in[17];
    const float* pw1_b    = (const float*)d_in[18];
    const float* dw_w     = (const float*)d_in[19];
    const float* dw_b     = (const float*)d_in[20];
    const float* pw2_w    = (const float*)d_in[21];
    const float* pw2_b    = (const float*)d_in[22];
    const float* leps     = (const float*)d_in[23];

    float *ff, *x1, *x2, *x3, *qkv, *pp, *sc, *ctx, *glu, *dsw, *wT;
    cudaGetSymbolAddress((void**)&ff,  g_ff);
    cudaGetSymbolAddress((void**)&x1,  g_x1);
    cudaGetSymbolAddress((void**)&x2,  g_x2);
    cudaGetSymbolAddress((void**)&x3,  g_x3);
    cudaGetSymbolAddress((void**)&qkv, g_qkv);
    cudaGetSymbolAddress((void**)&pp,  g_pproj);
    cudaGetSymbolAddress((void**)&sc,  g_scores);
    cudaGetSymbolAddress((void**)&ctx, g_ctx);
    cudaGetSymbolAddress((void**)&glu, g_glu);
    cudaGetSymbolAddress((void**)&dsw, g_dsw);
    cudaGetSymbolAddress((void**)&wT,  g_wT);

    const size_t smem_scores = (size_t)(3 * 64 * 65 + 64 * 128) * sizeof(float);
    cudaFuncSetAttribute(attn_scores_kernel, cudaFuncAttributeMaxDynamicSharedMemorySize,
                         (int)smem_scores);
    cudaFuncSetAttribute(gemm_nn_kernel<EPI_NONE>,  cudaFuncAttributeMaxDynamicSharedMemorySize, GEMM_SMEM);
    cudaFuncSetAttribute(gemm_nn_kernel<EPI_DSWISH>, cudaFuncAttributeMaxDynamicSharedMemorySize, GEMM_SMEM);
    cudaFuncSetAttribute(gemm_nn_kernel<EPI_RES>,   cudaFuncAttributeMaxDynamicSharedMemorySize, GEMM_SMEM);

    // 0) transpose weights: W (N x K) -> Wt (K x N)
    dim3 tb(32, 8);
    auto tgrid = [](int R, int C) { return dim3((C + 31) / 32, (R + 31) / 32); };
    transpose_kernel<<<tgrid(DFF_, E_), tb>>>(ffm_w1, wT + OFF_FFM_W1T, DFF_, E_);
    transpose_kernel<<<tgrid(E_, DFF_), tb>>>(ffm_w2, wT + OFF_FFM_W2T, E_, DFF_);
    transpose_kernel<<<tgrid(3 * E_, E_), tb>>>(in_w, wT + OFF_IN_WT, 3 * E_, E_);
    transpose_kernel<<<tgrid(E_, E_), tb>>>(wpos, wT + OFF_WPOST, E_, E_);
    transpose_kernel<<<tgrid(E_, E_), tb>>>(out_w, wT + OFF_OUT_WT, E_, E_);
    transpose_kernel<<<tgrid(2 * E_, E_), tb>>>(pw1_w, wT + OFF_PW1_WT, 2 * E_, E_);
    transpose_kernel<<<tgrid(E_, E_), tb>>>(pw2_w, wT + OFF_PW2_WT, E_, E_);
    transpose_kernel<<<tgrid(DFF_, E_), tb>>>(ff_w1, wT + OFF_FF_W1T, DFF_, E_);
    transpose_kernel<<<tgrid(E_, DFF_), tb>>>(ff_w2, wT + OFF_FF_W2T, E_, DFF_);

    // 1) macaron FFN
    gemm_nn_kernel<EPI_DSWISH><<<dim3(DFF_ / 128, NTOK / 128), 256, GEMM_SMEM>>>(
        src, wT + OFF_FFM_W1T, ffm_b1, nullptr, ff, NTOK, DFF_, E_);
    gemm_nn_kernel<EPI_RES><<<dim3(E_ / 128, NTOK / 128), 256, GEMM_SMEM>>>(
        ff, wT + OFF_FFM_W2T, ffm_b2, src, x1, NTOK, E_, DFF_);

    // 2) attention
    gemm_nn_kernel<EPI_NONE><<<dim3((3 * E_) / 128, NTOK / 128), 256, GEMM_SMEM>>>(
        x1, wT + OFF_IN_WT, in_b, nullptr, qkv, NTOK, 3 * E_, E_);
    gemm_nn_kernel<EPI_NONE><<<dim3(E_ / 128, (PLEN + 127) / 128), 256, GEMM_SMEM>>>(
        pos_emb, wT + OFF_WPOST, nullptr, nullptr, pp, PLEN, E_, E_);
    attn_scores_kernel<<<dim3(T_ / 64, T_ / 64, B_ * H_), 256, smem_scores>>>(qkv, pp, u, v, sc);
    softmax_kernel<<<B_ * H_ * T_, 256>>>(sc);
    attn_out_kernel<<<dim3(T_ / 64, B_ * H_), 256>>>(sc, qkv, ctx);
    gemm_nn_kernel<EPI_RES><<<dim3(E_ / 128, NTOK / 128), 256, GEMM_SMEM>>>(
        ctx, wT + OFF_OUT_WT, out_b, x1, x2, NTOK, E_, E_);

    // 3) conv module
    gemm_nn_kernel<EPI_NONE><<<dim3((2 * E_) / 128, NTOK / 128), 256, GEMM_SMEM>>>(
        x2, wT + OFF_PW1_WT, pw1_b, nullptr, ff, NTOK, 2 * E_, E_);
    glu_kernel<<<(NTOK * E_) / 256, 256>>>(ff, glu);
    dwconv_kernel<<<(NTOK * E_) / 256, 256>>>(glu, dw_w, dw_b, dsw);
    gemm_nn_kernel<EPI_RES><<<dim3(E_ / 128, NTOK / 128), 256, GEMM_SMEM>>>(
        dsw, wT + OFF_PW2_WT, pw2_b, x2, x3, NTOK, E_, E_);

    // 4) second FFN
    gemm_nn_kernel<EPI_DSWISH><<<dim3(DFF_ / 128, NTOK / 128), 256, GEMM_SMEM>>>(
        x3, wT + OFF_FF_W1T, ff_b1, nullptr, ff, NTOK, DFF_, E_);
    gemm_nn_kernel<EPI_RES><<<dim3(E_ / 128, NTOK / 128), 256, GEMM_SMEM>>>(
        ff, wT + OFF_FF_W2T, ff_b2, x3, x1, NTOK, E_, DFF_);

    // 5) BasicNorm -> output
    basic_norm_kernel<<<NTOK, 256>>>(x1, leps, (float*)d_out);
}

// round 5
// speedup vs baseline: 1.6036x; 1.3022x over previous
#include <cuda_runtime.h>
#include <cuda_bf16.h>
#include <math.h>
#include <stdint.h>

// ---------------- problem dims ----------------
#define T_    1024
#define B_    4
#define E_    512
#define H_    8
#define D_    64
#define DFF_  2048
#define NTOK  4096
#define PLEN  2047
#define KCONV 31

typedef unsigned long long u64;

// ---------------- scratch (device globals; no allocation) ----------------
__device__ float g_ff[NTOK * DFF_];
__device__ float g_x1[NTOK * E_];
__device__ float g_x2[NTOK * E_];
__device__ float g_x3[NTOK * E_];
__device__ float g_qkv[NTOK * 3 * E_];
__device__ float g_pproj[PLEN * E_];
__device__ float g_scores[32ull * T_ * T_];
__device__ float g_ctx[NTOK * E_];
__device__ float g_glu[NTOK * E_];
__device__ float g_dsw[NTOK * E_];
__device__ __nv_bfloat16 g_whi[7339520];
__device__ __nv_bfloat16 g_wlo[7339520];
__device__ __nv_bfloat16 g_ahi[NTOK * DFF_];
__device__ __nv_bfloat16 g_alo[NTOK * DFF_];

// packed weight offsets (elements)
#define OFF_FFM_W1 0
#define OFF_FFM_W2 1048576
#define OFF_IN_W   2097152
#define OFF_WPOS   2883584
#define OFF_OUT_W  3145728
#define OFF_PW1_W  3407872
#define OFF_PW2_W  3932160
#define OFF_FF_W1  4194304
#define OFF_FF_W2  5242880
#define OFF_POSE   6291456

__device__ __forceinline__ float sigmoidf_(float x) { return 1.f / (1.f + __expf(-x)); }

// ---------------- packed f32x2 helpers (attention kernels) ----------------
__device__ __forceinline__ u64 pack2_(float lo, float hi) {
    u64 r; asm("mov.b64 %0, {%1, %2};" : "=l"(r) : "f"(lo), "f"(hi)); return r;
}
__device__ __forceinline__ u64 pdup_(float x) {
    u64 r; asm("mov.b64 %0, {%1, %1};" : "=l"(r) : "f"(x)); return r;
}
__device__ __forceinline__ u64 ffma2_(u64 a, u64 b, u64 c) {
    u64 d; asm("fma.rn.f32x2 %0, %1, %2, %3;" : "=l"(d) : "l"(a), "l"(b), "l"(c)); return d;
}
__device__ __forceinline__ float2 unpack2_(u64 v) {
    float2 f; asm("mov.b64 {%0, %1}, %2;" : "=f"(f.x), "=f"(f.y) : "l"(v)); return f;
}
__device__ __forceinline__ uint32_t smem_u32_(const void* p) {
    return (uint32_t)__cvta_generic_to_shared(p);
}
__device__ __forceinline__ void cpasync16_(uint32_t dst, const void* src, int srcbytes) {
    asm volatile("cp.async.ca.shared.global [%0], [%1], 16, %2;"
                 :: "r"(dst), "l"(src), "r"(srcbytes));
}

// ---------------- hi/lo split into bf16 ----------------
__global__ void split_kernel(const float* __restrict__ x, __nv_bfloat16* __restrict__ hi,
                             __nv_bfloat16* __restrict__ lo, int n)
{
    int i = blockIdx.x * 256 + threadIdx.x;
    if (i < n) {
        float a = x[i];
        __nv_bfloat16 h = __float2bfloat16(a);
        hi[i] = h;
        lo[i] = __float2bfloat16(a - __bfloat162float(h));
    }
}

// ---------------- bf16 mma.sync NT GEMM (3-term compensated) ----------------
// C(MxN) = epi( A(MxK) * B(NxK)^T + bias ); accumulates Ahi*Bhi + Alo*Bhi + Ahi*Blo (fp32).
enum { EPI_NONE = 0, EPI_DSWISH = 1, EPI_RES = 2 };
#define SSTRIDE 40          // bf16 elements per shared row (80B, conflict-free)

template <int EPI>
__global__ void __launch_bounds__(256)
gemm_mma_kernel(const __nv_bfloat16* __restrict__ Ahi, const __nv_bfloat16* __restrict__ Alo,
                const __nv_bfloat16* __restrict__ Bhi, const __nv_bfloat16* __restrict__ Blo,
                const float* __restrict__ bias, const float* __restrict__ res,
                float* __restrict__ C, int M, int N, int K)
{
    __shared__ __nv_bfloat16 smA[2][128 * SSTRIDE];
    __shared__ __nv_bfloat16 smB[2][128 * SSTRIDE];

    const int tid = threadIdx.x;
    const int wid = tid >> 5;
    const int lane = tid & 31;
    const int m0 = blockIdx.y * 128, n0 = blockIdx.x * 128;
    const int nk = K >> 5;
    const int NI = 3 * nk;

    const int warp_m = wid & 1;        // 2 warp rows x 64
    const int warp_n = wid >> 1;       // 4 warp cols x 32
    const int mw = warp_m * 64;
    const int nw = warp_n * 32;

    float acc[4][4][4];
#pragma unroll
    for (int a = 0; a < 4; a++)
#pragma unroll
        for (int b = 0; b < 4; b++)
#pragma unroll
            for (int c = 0; c < 4; c++) acc[a][b][c] = 0.f;

    // cp.async load mapping: 2 chunks of 16B per array per thread
    const int lrow0 = tid >> 2,        lc0 = (tid & 3) << 3;          // bf16 col
    const int lrow1 = (tid + 256) >> 2, lc1 = ((tid + 256) & 3) << 3;
    const uint32_t smA_u = smem_u32_(smA);
    const uint32_t smB_u = smem_u32_(smB);
    const uint32_t adst0 = smA_u + (uint32_t)(lrow0 * SSTRIDE + lc0) * 2;
    const uint32_t adst1 = smA_u + (uint32_t)(lrow1 * SSTRIDE + lc1) * 2;
    const uint32_t bdst0 = smB_u + (uint32_t)(lrow0 * SSTRIDE + lc0) * 2;
    const uint32_t bdst1 = smB_u + (uint32_t)(lrow1 * SSTRIDE + lc1) * 2;
    const int am0 = m0 + lrow0, am1 = m0 + lrow1;
    const int stage_b = 128 * SSTRIDE * 2;   // bytes per stage

    auto issue_loads = [&](int kt) {
        int pass = (kt >= 2 * nk) ? 2 : ((kt >= nk) ? 1 : 0);
        int kk0 = (kt - pass * nk) << 5;
        const __nv_bfloat16* Asrc = (pass == 1) ? Alo : Ahi;
        const __nv_bfloat16* Bsrc = (pass == 2) ? Blo : Bhi;
        uint32_t so = (kt & 1) * stage_b;
        cpasync16_(adst0 + so, Asrc + (size_t)(am0 < M ? am0 : 0) * K + kk0 + lc0, am0 < M ? 16 : 0);
        cpasync16_(adst1 + so, Asrc + (size_t)(am1 < M ? am1 : 0) * K + kk0 + lc1, am1 < M ? 16 : 0);
        cpasync16_(bdst0 + so, Bsrc + (size_t)(n0 + lrow0) * K + kk0 + lc0, 16);
        cpasync16_(bdst1 + so, Bsrc + (size_t)(n0 + lrow1) * K + kk0 + lc1, 16);
    };

    issue_loads(0);
    asm volatile("cp.async.commit_group;" ::: "memory");

    // ldmatrix address components
    const int lr8 = lane & 7;
    const int sel = lane >> 3;               // 0..3
    // A: row = mw + mt*16 + lr8 + (sel&1)*8 ; col = kk*16 + (sel>>1)*8
    // B: row = nw + np*16 + lr8 + (sel>>1)*8 ; col = kk*16 + (sel&1)*8

    for (int kt = 0; kt < NI; kt++) {
        if (kt + 1 < NI) issue_loads(kt + 1);
        asm volatile("cp.async.commit_group;" ::: "memory");
        asm volatile("cp.async.wait_group 1;" ::: "memory");
        __syncthreads();

        const uint32_t aBase = smA_u + (kt & 1) * stage_b;
        const uint32_t bBase = smB_u + (kt & 1) * stage_b;
#pragma unroll
        for (int kk = 0; kk < 2; kk++) {
            uint32_t a[4][4];
#pragma unroll
            for (int mt = 0; mt < 4; mt++) {
                int row = mw + mt * 16 + lr8 + (sel & 1) * 8;
                int col = kk * 16 + (sel >> 1) * 8;
                uint32_t addr = aBase + (uint32_t)(row * SSTRIDE + col) * 2;
                asm volatile("ldmatrix.sync.aligned.m8n8.x4.shared.b16 {%0,%1,%2,%3}, [%4];"
                             : "=r"(a[mt][0]), "=r"(a[mt][1]), "=r"(a[mt][2]), "=r"(a[mt][3])
                             : "r"(addr));
            }
            uint32_t bfr[2][4];
#pragma unroll
            for (int np = 0; np < 2; np++) {
                int row = nw + np * 16 + lr8 + (sel >> 1) * 8;
                int col = kk * 16 + (sel & 1) * 8;
                uint32_t addr = bBase + (uint32_t)(row * SSTRIDE + col) * 2;
                asm volatile("ldmatrix.sync.aligned.m8n8.x4.shared.b16 {%0,%1,%2,%3}, [%4];"
                             : "=r"(bfr[np][0]), "=r"(bfr[np][1]), "=r"(bfr[np][2]), "=r"(bfr[np][3])
                             : "r"(addr));
            }
#pragma unroll
            for (int mt = 0; mt < 4; mt++) {
#pragma unroll
                for (int nt = 0; nt < 4; nt++) {
                    uint32_t b0 = bfr[nt >> 1][(nt & 1) * 2 + 0];
                    uint32_t b1 = bfr[nt >> 1][(nt & 1) * 2 + 1];
                    asm volatile(
                        "mma.sync.aligned.m16n8k16.row.col.f32.bf16.bf16.f32 "
                        "{%0,%1,%2,%3}, {%4,%5,%6,%7}, {%8,%9}, {%0,%1,%2,%3};"
                        : "+f"(acc[mt][nt][0]), "+f"(acc[mt][nt][1]),
                          "+f"(acc[mt][nt][2]), "+f"(acc[mt][nt][3])
                        : "r"(a[mt][0]), "r"(a[mt][1]), "r"(a[mt][2]), "r"(a[mt][3]),
                          "r"(b0), "r"(b1));
                }
            }
        }
        __syncthreads();
    }

    // epilogue
    const int g = lane >> 2, t4 = lane & 3;
#pragma unroll
    for (int mt = 0; mt < 4; mt++) {
#pragma unroll
        for (int rr = 0; rr < 2; rr++) {
            int row = m0 + mw + mt * 16 + g + rr * 8;
            if (row >= M) continue;
#pragma unroll
            for (int nt = 0; nt < 4; nt++) {
                int col = n0 + nw + nt * 8 + t4 * 2;
                float v0 = acc[mt][nt][rr * 2 + 0];
                float v1 = acc[mt][nt][rr * 2 + 1];
                if (bias) { v0 += bias[col]; v1 += bias[col + 1]; }
                if (EPI == EPI_DSWISH) {
                    v0 = v0 * sigmoidf_(v0 - 1.f);
                    v1 = v1 * sigmoidf_(v1 - 1.f);
                }
                size_t off = (size_t)row * N + col;
                if (EPI == EPI_RES) {
                    float2 rv = *(const float2*)&res[off];
                    v0 += rv.x; v1 += rv.y;
                }
                float2 o = make_float2(v0, v1);
                *(float2*)&C[off] = o;
            }
        }
    }
}

// ---------------- attention scores: scores = (q+u)K^T + rel_shift((q+v)P) ----------------
__global__ void attn_scores_kernel(const float* __restrict__ qkv,
                                   const float* __restrict__ pproj,
                                   const float* __restrict__ u,
                                   const float* __restrict__ v,
                                   float* __restrict__ scores)
{
    extern __shared__ float sm[];
    float* Qu = sm;
    float* Qv = Qu + 64 * 65;
    float* Kt = Qv + 64 * 65;
    float* Ps = Kt + 64 * 65;

    const int bh = blockIdx.z;
    const int b = bh >> 3, h = bh & 7;
    const int i0 = blockIdx.y * 64, j0 = blockIdx.x * 64;
    const int tid = threadIdx.x;
    const float scale = 0.125f;

    for (int idx = tid; idx < 64 * 64; idx += 256) {
        int li = idx >> 6, d = idx & 63;
        float q = qkv[(size_t)((i0 + li) * B_ + b) * (3 * E_) + h * 64 + d] * scale;
        Qu[li * 65 + d] = q + u[h * 64 + d];
        Qv[li * 65 + d] = q + v[h * 64 + d];
        Kt[li * 65 + d] = qkv[(size_t)((j0 + li) * B_ + b) * (3 * E_) + E_ + h * 64 + d];
    }
    const int m_min = (T_ - 1) - (i0 + 63) + j0;
    for (int idx = tid; idx < 64 * 127; idx += 256) {
        int d = idx / 127, mm = idx % 127;
        Ps[d * 128 + mm] = pproj[(size_t)(m_min + mm) * E_ + h * 64 + d];
    }
    __syncthreads();

    const int tm = (tid >> 4) << 2;
    const int tn = (tid & 15) << 2;
    const int base = 63 - tm + tn;
    u64 acc2[4][2];
#pragma unroll
    for (int i = 0; i < 4; i++) { acc2[i][0] = 0ull; acc2[i][1] = 0ull; }

#pragma unroll 4
    for (int d = 0; d < 64; d++) {
        u64 ad[4], cd[4];
#pragma unroll
        for (int ii = 0; ii < 4; ii++) {
            ad[ii] = pdup_(Qu[(tm + ii) * 65 + d]);
            cd[ii] = pdup_(Qv[(tm + ii) * 65 + d]);
        }
        float bb0 = Kt[(tn + 0) * 65 + d], bb1 = Kt[(tn + 1) * 65 + d];
        float bb2 = Kt[(tn + 2) * 65 + d], bb3 = Kt[(tn + 3) * 65 + d];
        u64 kb0 = pack2_(bb0, bb1), kb1 = pack2_(bb2, bb3);
        float p7[7];
#pragma unroll
        for (int t = 0; t < 7; t++) p7[t] = Ps[d * 128 + base + t - 3];
        u64 pp[6];
#pragma unroll
        for (int t = 0; t < 6; t++) pp[t] = pack2_(p7[t], p7[t + 1]);
#pragma unroll
        for (int ii = 0; ii < 4; ii++) {
            acc2[ii][0] = ffma2_(ad[ii], kb0, acc2[ii][0]);
            acc2[ii][1] = ffma2_(ad[ii], kb1, acc2[ii][1]);
            acc2[ii][0] = ffma2_(cd[ii], pp[3 - ii], acc2[ii][0]);
            acc2[ii][1] = ffma2_(cd[ii], pp[5 - ii], acc2[ii][1]);
        }
    }

    const size_t ob = ((size_t)bh * T_ + i0) * T_ + j0;
#pragma unroll
    for (int ii = 0; ii < 4; ii++) {
        float2 t0 = unpack2_(acc2[ii][0]);
        float2 t1 = unpack2_(acc2[ii][1]);
        float4 o = make_float4(t0.x, t0.y, t1.x, t1.y);
        *(float4*)&scores[ob + (size_t)(tm + ii) * T_ + tn] = o;
    }
}

// ---------------- softmax over rows of length 1024 (in place) ----------------
__global__ void softmax_kernel(float* __restrict__ s)
{
    __shared__ float red[8];
    __shared__ float red2[8];
    const int tid = threadIdx.x;
    float* p = s + (size_t)blockIdx.x * 1024;
    float v[4];
    float m = -1e30f;
#pragma unroll
    for (int i = 0; i < 4; i++) { v[i] = p[tid + i * 256]; m = fmaxf(m, v[i]); }
#pragma unroll
    for (int o = 16; o > 0; o >>= 1) m = fmaxf(m, __shfl_xor_sync(0xffffffffu, m, o));
    if ((tid & 31) == 0) red[tid >> 5] = m;
    __syncthreads();
    m = red[0];
#pragma unroll
    for (int i = 1; i < 8; i++) m = fmaxf(m, red[i]);

    float sum = 0.f;
#pragma unroll
    for (int i = 0; i < 4; i++) { v[i] = __expf(v[i] - m); sum += v[i]; }
#pragma unroll
    for (int o = 16; o > 0; o >>= 1) sum += __shfl_xor_sync(0xffffffffu, sum, o);
    if ((tid & 31) == 0) red2[tid >> 5] = sum;
    __syncthreads();
    sum = red2[0];
#pragma unroll
    for (int i = 1; i < 8; i++) sum += red2[i];
    float inv = 1.f / sum;
#pragma unroll
    for (int i = 0; i < 4; i++) p[tid + i * 256] = v[i] * inv;
}

// ---------------- attn @ V -> ctx in (T,B,E) layout ----------------
__global__ void attn_out_kernel(const float* __restrict__ scores,
                                const float* __restrict__ qkv,
                                float* __restrict__ ctx)
{
    __shared__ float As[64][33];
    __shared__ float Bs[32][68];
    const int bh = blockIdx.y;
    const int b = bh >> 3, h = bh & 7;
    const int i0 = blockIdx.x * 64;
    const int tid = threadIdx.x;
    const float* S = scores + ((size_t)bh * T_ + i0) * T_;
    const int tm = (tid >> 4) << 2;
    const int tn = (tid & 15) << 2;
    u64 acc[4][2];
#pragma unroll
    for (int i = 0; i < 4; i++) { acc[i][0] = 0ull; acc[i][1] = 0ull; }

    for (int k0 = 0; k0 < T_; k0 += 32) {
#pragma unroll
        for (int r = 0; r < 8; r++) {
            int idx = tid + r * 256;
            int ii = idx >> 5, kk = idx & 31;
            As[ii][kk] = S[(size_t)ii * T_ + k0 + kk];
        }
#pragma unroll
        for (int r = 0; r < 8; r++) {
            int idx = tid + r * 256;
            int kk = idx >> 6, d = idx & 63;
            Bs[kk][d] = qkv[(size_t)((k0 + kk) * B_ + b) * (3 * E_) + 2 * E_ + h * 64 + d];
        }
        __syncthreads();
#pragma unroll
        for (int kk = 0; kk < 32; kk++) {
            const ulonglong2* bp2 = (const ulonglong2*)&Bs[kk][tn];
            ulonglong2 bq = bp2[0];
#pragma unroll
            for (int x = 0; x < 4; x++) {
                u64 a = pdup_(As[tm + x][kk]);
                acc[x][0] = ffma2_(a, bq.x, acc[x][0]);
                acc[x][1] = ffma2_(a, bq.y, acc[x][1]);
            }
        }
        __syncthreads();
    }
#pragma unroll
    for (int x = 0; x < 4; x++) {
        int gi = i0 + tm + x;
        float2 t0 = unpack2_(acc[x][0]);
        float2 t1 = unpack2_(acc[x][1]);
        float4 o = make_float4(t0.x, t0.y, t1.x, t1.y);
        *(float4*)&ctx[(size_t)(gi * B_ + b) * E_ + h * 64 + tn] = o;
    }
}

// ---------------- GLU ----------------
__global__ void glu_kernel(const float* __restrict__ y, float* __restrict__ out)
{
    int idx = blockIdx.x * 256 + threadIdx.x;
    if (idx >= NTOK * E_) return;
    int r = idx >> 9, c = idx & 511;
    float a = y[(size_t)r * 1024 + c];
    float g = y[(size_t)r * 1024 + 512 + c];
    out[idx] = a * sigmoidf_(g);
}

// ---------------- depthwise conv (K=31, pad=15) + DoubleSwish ----------------
__global__ void dwconv_kernel(const float* __restrict__ x, const float* __restrict__ w,
                              const float* __restrict__ bias, float* __restrict__ out)
{
    int idx = blockIdx.x * 256 + threadIdx.x;
    if (idx >= NTOK * E_) return;
    int c = idx & 511;
    int tb = idx >> 9;
    int t = tb >> 2, b = tb & 3;
    float acc = bias[c];
#pragma unroll
    for (int k = 0; k < KCONV; k++) {
        int tt = t + k - 15;
        if (tt >= 0 && tt < T_)
            acc += x[(size_t)(tt * B_ + b) * E_ + c] * w[c * KCONV + k];
    }
    out[idx] = acc * sigmoidf_(acc - 1.f);
}

// ---------------- BasicNorm ----------------
__global__ void basic_norm_kernel(const float* __restrict__ x, const float* __restrict__ leps,
                                  float* __restrict__ out)
{
    __shared__ float red[8];
    const int tid = threadIdx.x;
    const float* p = x + (size_t)blockIdx.x * E_;
    float v0 = p[tid], v1 = p[tid + 256];
    float ss = v0 * v0 + v1 * v1;
#pragma unroll
    for (int o = 16; o > 0; o >>= 1) ss += __shfl_xor_sync(0xffffffffu, ss, o);
    if ((tid & 31) == 0) red[tid >> 5] = ss;
    __syncthreads();
    float tot = red[0];
#pragma unroll
    for (int i = 1; i < 8; i++) tot += red[i];
    float r = rsqrtf(tot * (1.f / (float)E_) + __expf(leps[0]));
    out[(size_t)blockIdx.x * E_ + tid]       = v0 * r;
    out[(size_t)blockIdx.x * E_ + tid + 256] = v1 * r;
}

// ---------------- launch ----------------
extern "C" void kernel_launch(void* const* d_in, const int* in_sizes, int n_in,
                              void* d_out, int out_size)
{
    const float* src      = (const float*)d_in[0];
    const float* pos_emb  = (const float*)d_in[1];
    const float* in_w     = (const float*)d_in[2];
    const float* in_b     = (const float*)d_in[3];
    const float* out_w    = (const float*)d_in[4];
    const float* out_b    = (const float*)d_in[5];
    const float* wpos     = (const float*)d_in[6];
    const float* u        = (const float*)d_in[7];
    const float* v        = (const float*)d_in[8];
    const float* ffm_w1   = (const float*)d_in[9];
    const float* ffm_b1   = (const float*)d_in[10];
    const float* ffm_w2   = (const float*)d_in[11];
    const float* ffm_b2   = (const float*)d_in[12];
    const float* ff_w1    = (const float*)d_in[13];
    const float* ff_b1    = (const float*)d_in[14];
    const float* ff_w2    = (const float*)d_in[15];
    const float* ff_b2    = (const float*)d_in[16];
    const float* pw1_w    = (const float*)d_in[17];
    const float* pw1_b    = (const float*)d_in[18];
    const float* dw_w     = (const float*)d_in[19];
    const float* dw_b     = (const float*)d_in[20];
    const float* pw2_w    = (const float*)d_in[21];
    const float* pw2_b    = (const float*)d_in[22];
    const float* leps     = (const float*)d_in[23];

    float *ff, *x1, *x2, *x3, *qkv, *pp, *sc, *ctx, *glu, *dsw;
    __nv_bfloat16 *whi, *wlo, *ahi, *alo;
    cudaGetSymbolAddress((void**)&ff,  g_ff);
    cudaGetSymbolAddress((void**)&x1,  g_x1);
    cudaGetSymbolAddress((void**)&x2,  g_x2);
    cudaGetSymbolAddress((void**)&x3,  g_x3);
    cudaGetSymbolAddress((void**)&qkv, g_qkv);
    cudaGetSymbolAddress((void**)&pp,  g_pproj);
    cudaGetSymbolAddress((void**)&sc,  g_scores);
    cudaGetSymbolAddress((void**)&ctx, g_ctx);
    cudaGetSymbolAddress((void**)&glu, g_glu);
    cudaGetSymbolAddress((void**)&dsw, g_dsw);
    cudaGetSymbolAddress((void**)&whi, g_whi);
    cudaGetSymbolAddress((void**)&wlo, g_wlo);
    cudaGetSymbolAddress((void**)&ahi, g_ahi);
    cudaGetSymbolAddress((void**)&alo, g_alo);

    const size_t smem_scores = (size_t)(3 * 64 * 65 + 64 * 128) * sizeof(float);
    cudaFuncSetAttribute(attn_scores_kernel, cudaFuncAttributeMaxDynamicSharedMemorySize,
                         (int)smem_scores);

    auto split = [&](const float* x, __nv_bfloat16* h, __nv_bfloat16* l, int n) {
        split_kernel<<<(n + 255) / 256, 256>>>(x, h, l, n);
    };

    // 0) split weights + pos_emb once
    split(ffm_w1,  whi + OFF_FFM_W1, wlo + OFF_FFM_W1, DFF_ * E_);
    split(ffm_w2,  whi + OFF_FFM_W2, wlo + OFF_FFM_W2, E_ * DFF_);
    split(in_w,    whi + OFF_IN_W,   wlo + OFF_IN_W,   3 * E_ * E_);
    split(wpos,    whi + OFF_WPOS,   wlo + OFF_WPOS,   E_ * E_);
    split(out_w,   whi + OFF_OUT_W,  wlo + OFF_OUT_W,  E_ * E_);
    split(pw1_w,   whi + OFF_PW1_W,  wlo + OFF_PW1_W,  2 * E_ * E_);
    split(pw2_w,   whi + OFF_PW2_W,  wlo + OFF_PW2_W,  E_ * E_);
    split(ff_w1,   whi + OFF_FF_W1,  wlo + OFF_FF_W1,  DFF_ * E_);
    split(ff_w2,   whi + OFF_FF_W2,  wlo + OFF_FF_W2,  E_ * DFF_);
    split(pos_emb, whi + OFF_POSE,   wlo + OFF_POSE,   PLEN * E_);

    // 1) macaron FFN
    split(src, ahi, alo, NTOK * E_);
    gemm_mma_kernel<EPI_DSWISH><<<dim3(DFF_ / 128, NTOK / 128), 256>>>(
        ahi, alo, whi + OFF_FFM_W1, wlo + OFF_FFM_W1, ffm_b1, nullptr, ff, NTOK, DFF_, E_);
    split(ff, ahi, alo, NTOK * DFF_);
    gemm_mma_kernel<EPI_RES><<<dim3(E_ / 128, NTOK / 128), 256>>>(
        ahi, alo, whi + OFF_FFM_W2, wlo + OFF_FFM_W2, ffm_b2, src, x1, NTOK, E_, DFF_);

    // 2) attention
    split(x1, ahi, alo, NTOK * E_);
    gemm_mma_kernel<EPI_NONE><<<dim3((3 * E_) / 128, NTOK / 128), 256>>>(
        ahi, alo, whi + OFF_IN_W, wlo + OFF_IN_W, in_b, nullptr, qkv, NTOK, 3 * E_, E_);
    gemm_mma_kernel<EPI_NONE><<<dim3(E_ / 128, (PLEN + 127) / 128), 256>>>(
        whi + OFF_POSE, wlo + OFF_POSE, whi + OFF_WPOS, wlo + OFF_WPOS,
        nullptr, nullptr, pp, PLEN, E_, E_);
    attn_scores_kernel<<<dim3(T_ / 64, T_ / 64, B_ * H_), 256, smem_scores>>>(qkv, pp, u, v, sc);
    softmax_kernel<<<B_ * H_ * T_, 256>>>(sc);
    attn_out_kernel<<<dim3(T_ / 64, B_ * H_), 256>>>(sc, qkv, ctx);
    split(ctx, ahi, alo, NTOK * E_);
    gemm_mma_kernel<EPI_RES><<<dim3(E_ / 128, NTOK / 128), 256>>>(
        ahi, alo, whi + OFF_OUT_W, wlo + OFF_OUT_W, out_b, x1, x2, NTOK, E_, E_);

    // 3) conv module
    split(x2, ahi, alo, NTOK * E_);
    gemm_mma_kernel<EPI_NONE><<<dim3((2 * E_) / 128, NTOK / 128), 256>>>(
        ahi, alo, whi + OFF_PW1_W, wlo + OFF_PW1_W, pw1_b, nullptr, ff, NTOK, 2 * E_, E_);
    glu_kernel<<<(NTOK * E_) / 256, 256>>>(ff, glu);
    dwconv_kernel<<<(NTOK * E_) / 256, 256>>>(glu, dw_w, dw_b, dsw);
    split(dsw, ahi, alo, NTOK * E_);
    gemm_mma_kernel<EPI_RES><<<dim3(E_ / 128, NTOK / 128), 256>>>(
        ahi, alo, whi + OFF_PW2_W, wlo + OFF_PW2_W, pw2_b, x2, x3, NTOK, E_, E_);

    // 4) second FFN
    split(x3, ahi, alo, NTOK * E_);
    gemm_mma_kernel<EPI_DSWISH><<<dim3(DFF_ / 128, NTOK / 128), 256>>>(
        ahi, alo, whi + OFF_FF_W1, wlo + OFF_FF_W1, ff_b1, nullptr, ff, NTOK, DFF_, E_);
    split(ff, ahi, alo, NTOK * DFF_);
    gemm_mma_kernel<EPI_RES><<<dim3(E_ / 128, NTOK / 128), 256>>>(
        ahi, alo, whi + OFF_FF_W2, wlo + OFF_FF_W2, ff_b2, x3, x1, NTOK, E_, DFF_);

    // 5) BasicNorm -> output
    basic_norm_kernel<<<NTOK, 256>>>(x1, leps, (float*)d_out);
}

// round 6
// speedup vs baseline: 1.6554x; 1.0323x over previous
#include <cuda_runtime.h>
#include <cuda_bf16.h>
#include <math.h>
#include <stdint.h>

// ---------------- problem dims ----------------
#define T_    1024
#define B_    4
#define E_    512
#define H_    8
#define D_    64
#define DFF_  2048
#define NTOK  4096
#define PLEN  2047
#define KCONV 31

typedef unsigned long long u64;

// ---------------- scratch (device globals; no allocation) ----------------
__device__ float g_ff[NTOK * DFF_];
__device__ float g_x1[NTOK * E_];
__device__ float g_x2[NTOK * E_];
__device__ float g_x3[NTOK * E_];
__device__ float g_qkv[NTOK * 3 * E_];
__device__ float g_pproj[PLEN * E_];
__device__ float g_scores[32ull * T_ * T_];
__device__ float g_glu[NTOK * E_];
__device__ __nv_bfloat16 g_whi[7339520];
__device__ __nv_bfloat16 g_wlo[7339520];
__device__ __nv_bfloat16 g_ahi[NTOK * DFF_];
__device__ __nv_bfloat16 g_alo[NTOK * DFF_];
__device__ __nv_bfloat16 g_bhi[NTOK * DFF_];
__device__ __nv_bfloat16 g_blo[NTOK * DFF_];

// packed weight offsets (elements)
#define OFF_FFM_W1 0
#define OFF_FFM_W2 1048576
#define OFF_IN_W   2097152
#define OFF_WPOS   2883584
#define OFF_OUT_W  3145728
#define OFF_PW1_W  3407872
#define OFF_PW2_W  3932160
#define OFF_FF_W1  4194304
#define OFF_FF_W2  5242880
#define OFF_POSE   6291456

__device__ __forceinline__ float sigmoidf_(float x) { return 1.f / (1.f + __expf(-x)); }

// ---------------- packed f32x2 helpers (attention kernels) ----------------
__device__ __forceinline__ u64 pack2_(float lo, float hi) {
    u64 r; asm("mov.b64 %0, {%1, %2};" : "=l"(r) : "f"(lo), "f"(hi)); return r;
}
__device__ __forceinline__ u64 pdup_(float x) {
    u64 r; asm("mov.b64 %0, {%1, %1};" : "=l"(r) : "f"(x)); return r;
}
__device__ __forceinline__ u64 ffma2_(u64 a, u64 b, u64 c) {
    u64 d; asm("fma.rn.f32x2 %0, %1, %2, %3;" : "=l"(d) : "l"(a), "l"(b), "l"(c)); return d;
}
__device__ __forceinline__ float2 unpack2_(u64 v) {
    float2 f; asm("mov.b64 {%0, %1}, %2;" : "=f"(f.x), "=f"(f.y) : "l"(v)); return f;
}
__device__ __forceinline__ uint32_t smem_u32_(const void* p) {
    return (uint32_t)__cvta_generic_to_shared(p);
}
__device__ __forceinline__ void cpasync16_(uint32_t dst, const void* src, int srcbytes) {
    asm volatile("cp.async.ca.shared.global [%0], [%1], 16, %2;"
                 :: "r"(dst), "l"(src), "r"(srcbytes));
}
__device__ __forceinline__ void split2_(float v0, float v1,
                                        __nv_bfloat16* hi, __nv_bfloat16* lo, size_t off) {
    __nv_bfloat16 h0 = __float2bfloat16(v0);
    __nv_bfloat16 h1 = __float2bfloat16(v1);
    __nv_bfloat162 hp; hp.x = h0; hp.y = h1;
    __nv_bfloat162 lp;
    lp.x = __float2bfloat16(v0 - __bfloat162float(h0));
    lp.y = __float2bfloat16(v1 - __bfloat162float(h1));
    *(__nv_bfloat162*)(hi + off) = hp;
    *(__nv_bfloat162*)(lo + off) = lp;
}

// ---------------- hi/lo split into bf16 ----------------
__global__ void split_kernel(const float* __restrict__ x, __nv_bfloat16* __restrict__ hi,
                             __nv_bfloat16* __restrict__ lo, int n)
{
    int i = blockIdx.x * 256 + threadIdx.x;
    if (i < n) {
        float a = x[i];
        __nv_bfloat16 h = __float2bfloat16(a);
        hi[i] = h;
        lo[i] = __float2bfloat16(a - __bfloat162float(h));
    }
}

// ---------------- bf16 mma.sync NT GEMM (3-term compensated) ----------------
// C(MxN) = epi( A(MxK) * B(NxK)^T + bias ); acc = Ahi*Bhi + Alo*Bhi + Ahi*Blo (fp32).
enum { EPI_NONE = 0, EPI_DSWISH = 1, EPI_RES = 2 };
#define SSTRIDE 40

template <int EPI, int WC, int WS>
__global__ void __launch_bounds__(256)
gemm_mma_kernel(const __nv_bfloat16* __restrict__ Ahi, const __nv_bfloat16* __restrict__ Alo,
                const __nv_bfloat16* __restrict__ Bhi, const __nv_bfloat16* __restrict__ Blo,
                const float* __restrict__ bias, const float* __restrict__ res,
                float* __restrict__ C,
                __nv_bfloat16* __restrict__ Ohi, __nv_bfloat16* __restrict__ Olo,
                int M, int N, int K)
{
    __shared__ __nv_bfloat16 smA[2][128 * SSTRIDE];
    __shared__ __nv_bfloat16 smB[2][128 * SSTRIDE];

    const int tid = threadIdx.x;
    const int wid = tid >> 5;
    const int lane = tid & 31;
    const int m0 = blockIdx.y * 128, n0 = blockIdx.x * 128;
    const int nk = K >> 5;
    const int NI = 3 * nk;

    const int mw = (wid & 1) * 64;
    const int nw = (wid >> 1) * 32;

    float acc[4][4][4];
#pragma unroll
    for (int a = 0; a < 4; a++)
#pragma unroll
        for (int b = 0; b < 4; b++)
#pragma unroll
            for (int c = 0; c < 4; c++) acc[a][b][c] = 0.f;

    const int lrow0 = tid >> 2,         lc0 = (tid & 3) << 3;
    const int lrow1 = (tid + 256) >> 2, lc1 = ((tid + 256) & 3) << 3;
    const uint32_t smA_u = smem_u32_(smA);
    const uint32_t smB_u = smem_u32_(smB);
    const uint32_t adst0 = smA_u + (uint32_t)(lrow0 * SSTRIDE + lc0) * 2;
    const uint32_t adst1 = smA_u + (uint32_t)(lrow1 * SSTRIDE + lc1) * 2;
    const uint32_t bdst0 = smB_u + (uint32_t)(lrow0 * SSTRIDE + lc0) * 2;
    const uint32_t bdst1 = smB_u + (uint32_t)(lrow1 * SSTRIDE + lc1) * 2;
    const int am0 = m0 + lrow0, am1 = m0 + lrow1;
    const int stage_b = 128 * SSTRIDE * 2;

    auto issue_loads = [&](int kt) {
        int pass = (kt >= 2 * nk) ? 2 : ((kt >= nk) ? 1 : 0);
        int kk0 = (kt - pass * nk) << 5;
        const __nv_bfloat16* Asrc = (pass == 1) ? Alo : Ahi;
        const __nv_bfloat16* Bsrc = (pass == 2) ? Blo : Bhi;
        uint32_t so = (kt & 1) * stage_b;
        cpasync16_(adst0 + so, Asrc + (size_t)(am0 < M ? am0 : 0) * K + kk0 + lc0, am0 < M ? 16 : 0);
        cpasync16_(adst1 + so, Asrc + (size_t)(am1 < M ? am1 : 0) * K + kk0 + lc1, am1 < M ? 16 : 0);
        cpasync16_(bdst0 + so, Bsrc + (size_t)(n0 + lrow0) * K + kk0 + lc0, 16);
        cpasync16_(bdst1 + so, Bsrc + (size_t)(n0 + lrow1) * K + kk0 + lc1, 16);
    };

    issue_loads(0);
    asm volatile("cp.async.commit_group;" ::: "memory");

    const int lr8 = lane & 7;
    const int sel = lane >> 3;

    for (int kt = 0; kt < NI; kt++) {
        if (kt + 1 < NI) issue_loads(kt + 1);
        asm volatile("cp.async.commit_group;" ::: "memory");
        asm volatile("cp.async.wait_group 1;" ::: "memory");
        __syncthreads();

        const uint32_t aBase = smA_u + (kt & 1) * stage_b;
        const uint32_t bBase = smB_u + (kt & 1) * stage_b;
#pragma unroll
        for (int kk = 0; kk < 2; kk++) {
            uint32_t a[4][4];
#pragma unroll
            for (int mt = 0; mt < 4; mt++) {
                int row = mw + mt * 16 + lr8 + (sel & 1) * 8;
                int col = kk * 16 + (sel >> 1) * 8;
                uint32_t addr = aBase + (uint32_t)(row * SSTRIDE + col) * 2;
                asm volatile("ldmatrix.sync.aligned.m8n8.x4.shared.b16 {%0,%1,%2,%3}, [%4];"
                             : "=r"(a[mt][0]), "=r"(a[mt][1]), "=r"(a[mt][2]), "=r"(a[mt][3])
                             : "r"(addr));
            }
            uint32_t bfr[2][4];
#pragma unroll
            for (int np = 0; np < 2; np++) {
                int row = nw + np * 16 + lr8 + (sel >> 1) * 8;
                int col = kk * 16 + (sel & 1) * 8;
                uint32_t addr = bBase + (uint32_t)(row * SSTRIDE + col) * 2;
                asm volatile("ldmatrix.sync.aligned.m8n8.x4.shared.b16 {%0,%1,%2,%3}, [%4];"
                             : "=r"(bfr[np][0]), "=r"(bfr[np][1]), "=r"(bfr[np][2]), "=r"(bfr[np][3])
                             : "r"(addr));
            }
#pragma unroll
            for (int mt = 0; mt < 4; mt++) {
#pragma unroll
                for (int nt = 0; nt < 4; nt++) {
                    uint32_t b0 = bfr[nt >> 1][(nt & 1) * 2 + 0];
                    uint32_t b1 = bfr[nt >> 1][(nt & 1) * 2 + 1];
                    asm volatile(
                        "mma.sync.aligned.m16n8k16.row.col.f32.bf16.bf16.f32 "
                        "{%0,%1,%2,%3}, {%4,%5,%6,%7}, {%8,%9}, {%0,%1,%2,%3};"
                        : "+f"(acc[mt][nt][0]), "+f"(acc[mt][nt][1]),
                          "+f"(acc[mt][nt][2]), "+f"(acc[mt][nt][3])
                        : "r"(a[mt][0]), "r"(a[mt][1]), "r"(a[mt][2]), "r"(a[mt][3]),
                          "r"(b0), "r"(b1));
                }
            }
        }
        __syncthreads();
    }

    // epilogue
    const int g = lane >> 2, t4 = lane & 3;
#pragma unroll
    for (int mt = 0; mt < 4; mt++) {
#pragma unroll
        for (int rr = 0; rr < 2; rr++) {
            int row = m0 + mw + mt * 16 + g + rr * 8;
            if (row >= M) continue;
#pragma unroll
            for (int nt = 0; nt < 4; nt++) {
                int col = n0 + nw + nt * 8 + t4 * 2;
                float v0 = acc[mt][nt][rr * 2 + 0];
                float v1 = acc[mt][nt][rr * 2 + 1];
                if (bias) { v0 += bias[col]; v1 += bias[col + 1]; }
                if (EPI == EPI_DSWISH) {
                    v0 = v0 * sigmoidf_(v0 - 1.f);
                    v1 = v1 * sigmoidf_(v1 - 1.f);
                }
                size_t off = (size_t)row * N + col;
                if (EPI == EPI_RES) {
                    float2 rv = *(const float2*)&res[off];
                    v0 += rv.x; v1 += rv.y;
                }
                if (WC) *(float2*)&C[off] = make_float2(v0, v1);
                if (WS) split2_(v0, v1, Ohi, Olo, off);
            }
        }
    }
}

// ---------------- attention scores ----------------
__global__ void attn_scores_kernel(const float* __restrict__ qkv,
                                   const float* __restrict__ pproj,
                                   const float* __restrict__ u,
                                   const float* __restrict__ v,
                                   float* __restrict__ scores)
{
    extern __shared__ float sm[];
    float* Qu = sm;
    float* Qv = Qu + 64 * 65;
    float* Kt = Qv + 64 * 65;
    float* Ps = Kt + 64 * 65;

    const int bh = blockIdx.z;
    const int b = bh >> 3, h = bh & 7;
    const int i0 = blockIdx.y * 64, j0 = blockIdx.x * 64;
    const int tid = threadIdx.x;
    const float scale = 0.125f;

    for (int idx = tid; idx < 64 * 64; idx += 256) {
        int li = idx >> 6, d = idx & 63;
        float q = qkv[(size_t)((i0 + li) * B_ + b) * (3 * E_) + h * 64 + d] * scale;
        Qu[li * 65 + d] = q + u[h * 64 + d];
        Qv[li * 65 + d] = q + v[h * 64 + d];
        Kt[li * 65 + d] = qkv[(size_t)((j0 + li) * B_ + b) * (3 * E_) + E_ + h * 64 + d];
    }
    const int m_min = (T_ - 1) - (i0 + 63) + j0;
    for (int idx = tid; idx < 64 * 127; idx += 256) {
        int d = idx / 127, mm = idx % 127;
        Ps[d * 128 + mm] = pproj[(size_t)(m_min + mm) * E_ + h * 64 + d];
    }
    __syncthreads();

    const int tm = (tid >> 4) << 2;
    const int tn = (tid & 15) << 2;
    const int base = 63 - tm + tn;
    u64 acc2[4][2];
#pragma unroll
    for (int i = 0; i < 4; i++) { acc2[i][0] = 0ull; acc2[i][1] = 0ull; }

#pragma unroll 4
    for (int d = 0; d < 64; d++) {
        u64 ad[4], cd[4];
#pragma unroll
        for (int ii = 0; ii < 4; ii++) {
            ad[ii] = pdup_(Qu[(tm + ii) * 65 + d]);
            cd[ii] = pdup_(Qv[(tm + ii) * 65 + d]);
        }
        float bb0 = Kt[(tn + 0) * 65 + d], bb1 = Kt[(tn + 1) * 65 + d];
        float bb2 = Kt[(tn + 2) * 65 + d], bb3 = Kt[(tn + 3) * 65 + d];
        u64 kb0 = pack2_(bb0, bb1), kb1 = pack2_(bb2, bb3);
        float p7[7];
#pragma unroll
        for (int t = 0; t < 7; t++) p7[t] = Ps[d * 128 + base + t - 3];
        u64 pp[6];
#pragma unroll
        for (int t = 0; t < 6; t++) pp[t] = pack2_(p7[t], p7[t + 1]);
#pragma unroll
        for (int ii = 0; ii < 4; ii++) {
            acc2[ii][0] = ffma2_(ad[ii], kb0, acc2[ii][0]);
            acc2[ii][1] = ffma2_(ad[ii], kb1, acc2[ii][1]);
            acc2[ii][0] = ffma2_(cd[ii], pp[3 - ii], acc2[ii][0]);
            acc2[ii][1] = ffma2_(cd[ii], pp[5 - ii], acc2[ii][1]);
        }
    }

    const size_t ob = ((size_t)bh * T_ + i0) * T_ + j0;
#pragma unroll
    for (int ii = 0; ii < 4; ii++) {
        float2 t0 = unpack2_(acc2[ii][0]);
        float2 t1 = unpack2_(acc2[ii][1]);
        float4 o = make_float4(t0.x, t0.y, t1.x, t1.y);
        *(float4*)&scores[ob + (size_t)(tm + ii) * T_ + tn] = o;
    }
}

// ---------------- softmax over rows of length 1024 (in place) ----------------
__global__ void softmax_kernel(float* __restrict__ s)
{
    __shared__ float red[8];
    __shared__ float red2[8];
    const int tid = threadIdx.x;
    float* p = s + (size_t)blockIdx.x * 1024;
    float v[4];
    float m = -1e30f;
#pragma unroll
    for (int i = 0; i < 4; i++) { v[i] = p[tid + i * 256]; m = fmaxf(m, v[i]); }
#pragma unroll
    for (int o = 16; o > 0; o >>= 1) m = fmaxf(m, __shfl_xor_sync(0xffffffffu, m, o));
    if ((tid & 31) == 0) red[tid >> 5] = m;
    __syncthreads();
    m = red[0];
#pragma unroll
    for (int i = 1; i < 8; i++) m = fmaxf(m, red[i]);

    float sum = 0.f;
#pragma unroll
    for (int i = 0; i < 4; i++) { v[i] = __expf(v[i] - m); sum += v[i]; }
#pragma unroll
    for (int o = 16; o > 0; o >>= 1) sum += __shfl_xor_sync(0xffffffffu, sum, o);
    if ((tid & 31) == 0) red2[tid >> 5] = sum;
    __syncthreads();
    sum = red2[0];
#pragma unroll
    for (int i = 1; i < 8; i++) sum += red2[i];
    float inv = 1.f / sum;
#pragma unroll
    for (int i = 0; i < 4; i++) p[tid + i * 256] = v[i] * inv;
}

// ---------------- attn @ V -> ctx split bf16 in (T,B,E) layout ----------------
__global__ void attn_out_kernel(const float* __restrict__ scores,
                                const float* __restrict__ qkv,
                                __nv_bfloat16* __restrict__ chi,
                                __nv_bfloat16* __restrict__ clo)
{
    __shared__ float As[64][33];
    __shared__ float Bs[32][68];
    const int bh = blockIdx.y;
    const int b = bh >> 3, h = bh & 7;
    const int i0 = blockIdx.x * 64;
    const int tid = threadIdx.x;
    const float* S = scores + ((size_t)bh * T_ + i0) * T_;
    const int tm = (tid >> 4) << 2;
    const int tn = (tid & 15) << 2;
    u64 acc[4][2];
#pragma unroll
    for (int i = 0; i < 4; i++) { acc[i][0] = 0ull; acc[i][1] = 0ull; }

    for (int k0 = 0; k0 < T_; k0 += 32) {
#pragma unroll
        for (int r = 0; r < 8; r++) {
            int idx = tid + r * 256;
            int ii = idx >> 5, kk = idx & 31;
            As[ii][kk] = S[(size_t)ii * T_ + k0 + kk];
        }
#pragma unroll
        for (int r = 0; r < 8; r++) {
            int idx = tid + r * 256;
            int kk = idx >> 6, d = idx & 63;
            Bs[kk][d] = qkv[(size_t)((k0 + kk) * B_ + b) * (3 * E_) + 2 * E_ + h * 64 + d];
        }
        __syncthreads();
#pragma unroll
        for (int kk = 0; kk < 32; kk++) {
            const ulonglong2* bp2 = (const ulonglong2*)&Bs[kk][tn];
            ulonglong2 bq = bp2[0];
#pragma unroll
            for (int x = 0; x < 4; x++) {
                u64 a = pdup_(As[tm + x][kk]);
                acc[x][0] = ffma2_(a, bq.x, acc[x][0]);
                acc[x][1] = ffma2_(a, bq.y, acc[x][1]);
            }
        }
        __syncthreads();
    }
#pragma unroll
    for (int x = 0; x < 4; x++) {
        int gi = i0 + tm + x;
        float2 t0 = unpack2_(acc[x][0]);
        float2 t1 = unpack2_(acc[x][1]);
        size_t off = (size_t)(gi * B_ + b) * E_ + h * 64 + tn;
        split2_(t0.x, t0.y, chi, clo, off);
        split2_(t1.x, t1.y, chi, clo, off + 2);
    }
}

// ---------------- GLU ----------------
__global__ void glu_kernel(const float* __restrict__ y, float* __restrict__ out)
{
    int idx = blockIdx.x * 256 + threadIdx.x;
    if (idx >= NTOK * E_) return;
    int r = idx >> 9, c = idx & 511;
    float a = y[(size_t)r * 1024 + c];
    float g = y[(size_t)r * 1024 + 512 + c];
    out[idx] = a * sigmoidf_(g);
}

// ---------------- depthwise conv + DoubleSwish -> split bf16 ----------------
__global__ void dwconv_kernel(const float* __restrict__ x, const float* __restrict__ w,
                              const float* __restrict__ bias,
                              __nv_bfloat16* __restrict__ ohi, __nv_bfloat16* __restrict__ olo)
{
    int idx = blockIdx.x * 256 + threadIdx.x;
    if (idx >= NTOK * E_) return;
    int c = idx & 511;
    int tb = idx >> 9;
    int t = tb >> 2, b = tb & 3;
    float acc = bias[c];
#pragma unroll
    for (int k = 0; k < KCONV; k++) {
        int tt = t + k - 15;
        if (tt >= 0 && tt < T_)
            acc += x[(size_t)(tt * B_ + b) * E_ + c] * w[c * KCONV + k];
    }
    float vv = acc * sigmoidf_(acc - 1.f);
    __nv_bfloat16 h = __float2bfloat16(vv);
    ohi[idx] = h;
    olo[idx] = __float2bfloat16(vv - __bfloat162float(h));
}

// ---------------- BasicNorm ----------------
__global__ void basic_norm_kernel(const float* __restrict__ x, const float* __restrict__ leps,
                                  float* __restrict__ out)
{
    __shared__ float red[8];
    const int tid = threadIdx.x;
    const float* p = x + (size_t)blockIdx.x * E_;
    float v0 = p[tid], v1 = p[tid + 256];
    float ss = v0 * v0 + v1 * v1;
#pragma unroll
    for (int o = 16; o > 0; o >>= 1) ss += __shfl_xor_sync(0xffffffffu, ss, o);
    if ((tid & 31) == 0) red[tid >> 5] = ss;
    __syncthreads();
    float tot = red[0];
#pragma unroll
    for (int i = 1; i < 8; i++) tot += red[i];
    float r = rsqrtf(tot * (1.f / (float)E_) + __expf(leps[0]));
    out[(size_t)blockIdx.x * E_ + tid]       = v0 * r;
    out[(size_t)blockIdx.x * E_ + tid + 256] = v1 * r;
}

// ---------------- launch ----------------
extern "C" void kernel_launch(void* const* d_in, const int* in_sizes, int n_in,
                              void* d_out, int out_size)
{
    const float* src      = (const float*)d_in[0];
    const float* pos_emb  = (const float*)d_in[1];
    const float* in_w     = (const float*)d_in[2];
    const float* in_b     = (const float*)d_in[3];
    const float* out_w    = (const float*)d_in[4];
    const float* out_b    = (const float*)d_in[5];
    const float* wpos     = (const float*)d_in[6];
    const float* u        = (const float*)d_in[7];
    const float* v        = (const float*)d_in[8];
    const float* ffm_w1   = (const float*)d_in[9];
    const float* ffm_b1   = (const float*)d_in[10];
    const float* ffm_w2   = (const float*)d_in[11];
    const float* ffm_b2   = (const float*)d_in[12];
    const float* ff_w1    = (const float*)d_in[13];
    const float* ff_b1    = (const float*)d_in[14];
    const float* ff_w2    = (const float*)d_in[15];
    const float* ff_b2    = (const float*)d_in[16];
    const float* pw1_w    = (const float*)d_in[17];
    const float* pw1_b    = (const float*)d_in[18];
    const float* dw_w     = (const float*)d_in[19];
    const float* dw_b     = (const float*)d_in[20];
    const float* pw2_w    = (const float*)d_in[21];
    const float* pw2_b    = (const float*)d_in[22];
    const float* leps     = (const float*)d_in[23];

    float *ff, *x1, *x2, *x3, *qkv, *pp, *sc, *glu;
    __nv_bfloat16 *whi, *wlo, *ahi, *alo, *bhi, *blo;
    cudaGetSymbolAddress((void**)&ff,  g_ff);
    cudaGetSymbolAddress((void**)&x1,  g_x1);
    cudaGetSymbolAddress((void**)&x2,  g_x2);
    cudaGetSymbolAddress((void**)&x3,  g_x3);
    cudaGetSymbolAddress((void**)&qkv, g_qkv);
    cudaGetSymbolAddress((void**)&pp,  g_pproj);
    cudaGetSymbolAddress((void**)&sc,  g_scores);
    cudaGetSymbolAddress((void**)&glu, g_glu);
    cudaGetSymbolAddress((void**)&whi, g_whi);
    cudaGetSymbolAddress((void**)&wlo, g_wlo);
    cudaGetSymbolAddress((void**)&ahi, g_ahi);
    cudaGetSymbolAddress((void**)&alo, g_alo);
    cudaGetSymbolAddress((void**)&bhi, g_bhi);
    cudaGetSymbolAddress((void**)&blo, g_blo);

    const size_t smem_scores = (size_t)(3 * 64 * 65 + 64 * 128) * sizeof(float);
    cudaFuncSetAttribute(attn_scores_kernel, cudaFuncAttributeMaxDynamicSharedMemorySize,
                         (int)smem_scores);

    auto split = [&](const float* x, __nv_bfloat16* h, __nv_bfloat16* l, int n) {
        split_kernel<<<(n + 255) / 256, 256>>>(x, h, l, n);
    };

    // 0) split weights + pos_emb once
    split(ffm_w1,  whi + OFF_FFM_W1, wlo + OFF_FFM_W1, DFF_ * E_);
    split(ffm_w2,  whi + OFF_FFM_W2, wlo + OFF_FFM_W2, E_ * DFF_);
    split(in_w,    whi + OFF_IN_W,   wlo + OFF_IN_W,   3 * E_ * E_);
    split(wpos,    whi + OFF_WPOS,   wlo + OFF_WPOS,   E_ * E_);
    split(out_w,   whi + OFF_OUT_W,  wlo + OFF_OUT_W,  E_ * E_);
    split(pw1_w,   whi + OFF_PW1_W,  wlo + OFF_PW1_W,  2 * E_ * E_);
    split(pw2_w,   whi + OFF_PW2_W,  wlo + OFF_PW2_W,  E_ * E_);
    split(ff_w1,   whi + OFF_FF_W1,  wlo + OFF_FF_W1,  DFF_ * E_);
    split(ff_w2,   whi + OFF_FF_W2,  wlo + OFF_FF_W2,  E_ * DFF_);
    split(pos_emb, whi + OFF_POSE,   wlo + OFF_POSE,   PLEN * E_);

    // 1) macaron FFN: src->A; FFN1 writes split only to B; FFN2 writes x1 fp32 + split A
    split(src, ahi, alo, NTOK * E_);
    gemm_mma_kernel<EPI_DSWISH, 0, 1><<<dim3(DFF_ / 128, NTOK / 128), 256>>>(
        ahi, alo, whi + OFF_FFM_W1, wlo + OFF_FFM_W1, ffm_b1, nullptr,
        nullptr, bhi, blo, NTOK, DFF_, E_);
    gemm_mma_kernel<EPI_RES, 1, 1><<<dim3(E_ / 128, NTOK / 128), 256>>>(
        bhi, blo, whi + OFF_FFM_W2, wlo + OFF_FFM_W2, ffm_b2, src,
        x1, ahi, alo, NTOK, E_, DFF_);

    // 2) attention
    gemm_mma_kernel<EPI_NONE, 1, 0><<<dim3((3 * E_) / 128, NTOK / 128), 256>>>(
        ahi, alo, whi + OFF_IN_W, wlo + OFF_IN_W, in_b, nullptr,
        qkv, nullptr, nullptr, NTOK, 3 * E_, E_);
    gemm_mma_kernel<EPI_NONE, 1, 0><<<dim3(E_ / 128, (PLEN + 127) / 128), 256>>>(
        whi + OFF_POSE, wlo + OFF_POSE, whi + OFF_WPOS, wlo + OFF_WPOS, nullptr, nullptr,
        pp, nullptr, nullptr, PLEN, E_, E_);
    attn_scores_kernel<<<dim3(T_ / 64, T_ / 64, B_ * H_), 256, smem_scores>>>(qkv, pp, u, v, sc);
    softmax_kernel<<<B_ * H_ * T_, 256>>>(sc);
    attn_out_kernel<<<dim3(T_ / 64, B_ * H_), 256>>>(sc, qkv, bhi, blo);
    gemm_mma_kernel<EPI_RES, 1, 1><<<dim3(E_ / 128, NTOK / 128), 256>>>(
        bhi, blo, whi + OFF_OUT_W, wlo + OFF_OUT_W, out_b, x1,
        x2, ahi, alo, NTOK, E_, E_);

    // 3) conv module
    gemm_mma_kernel<EPI_NONE, 1, 0><<<dim3((2 * E_) / 128, NTOK / 128), 256>>>(
        ahi, alo, whi + OFF_PW1_W, wlo + OFF_PW1_W, pw1_b, nullptr,
        ff, nullptr, nullptr, NTOK, 2 * E_, E_);
    glu_kernel<<<(NTOK * E_) / 256, 256>>>(ff, glu);
    dwconv_kernel<<<(NTOK * E_) / 256, 256>>>(glu, dw_w, dw_b, bhi, blo);
    gemm_mma_kernel<EPI_RES, 1, 1><<<dim3(E_ / 128, NTOK / 128), 256>>>(
        bhi, blo, whi + OFF_PW2_W, wlo + OFF_PW2_W, pw2_b, x2,
        x3, ahi, alo, NTOK, E_, E_);

    // 4) second FFN
    gemm_mma_kernel<EPI_DSWISH, 0, 1><<<dim3(DFF_ / 128, NTOK / 128), 256>>>(
        ahi, alo, whi + OFF_FF_W1, wlo + OFF_FF_W1, ff_b1, nullptr,
        nullptr, bhi, blo, NTOK, DFF_, E_);
    gemm_mma_kernel<EPI_RES, 1, 0><<<dim3(E_ / 128, NTOK / 128), 256>>>(
        bhi, blo, whi + OFF_FF_W2, wlo + OFF_FF_W2, ff_b2, x3,
        x1, nullptr, nullptr, NTOK, E_, DFF_);

    // 5) BasicNorm -> output
    basic_norm_kernel<<<NTOK, 256>>>(x1, leps, (float*)d_out);
}

// round 7
// speedup vs baseline: 1.6811x; 1.0155x over previous
#include <cuda_runtime.h>
#include <cuda_bf16.h>
#include <math.h>
#include <stdint.h>

// ---------------- problem dims ----------------
#define T_    1024
#define B_    4
#define E_    512
#define H_    8
#define D_    64
#define DFF_  2048
#define NTOK  4096
#define PLEN  2047
#define KCONV 31

typedef unsigned long long u64;

// ---------------- scratch (device globals; no allocation) ----------------
__device__ float g_ff[NTOK * DFF_];
__device__ float g_x1[NTOK * E_];
__device__ float g_x2[NTOK * E_];
__device__ float g_x3[NTOK * E_];
__device__ float g_qkv[NTOK * 3 * E_];
__device__ float g_pproj[PLEN * E_];
__device__ float g_glu[NTOK * E_];
__device__ __nv_bfloat16 g_whi[7339520];
__device__ __nv_bfloat16 g_wlo[7339520];
__device__ __nv_bfloat16 g_ahi[NTOK * DFF_];
__device__ __nv_bfloat16 g_alo[NTOK * DFF_];
__device__ __nv_bfloat16 g_bhi[NTOK * DFF_];
__device__ __nv_bfloat16 g_blo[NTOK * DFF_];

// packed weight offsets (elements)
#define OFF_FFM_W1 0
#define OFF_FFM_W2 1048576
#define OFF_IN_W   2097152
#define OFF_WPOS   2883584
#define OFF_OUT_W  3145728
#define OFF_PW1_W  3407872
#define OFF_PW2_W  3932160
#define OFF_FF_W1  4194304
#define OFF_FF_W2  5242880
#define OFF_POSE   6291456

__device__ __forceinline__ float sigmoidf_(float x) { return 1.f / (1.f + __expf(-x)); }

// ---------------- packed f32x2 helpers ----------------
__device__ __forceinline__ u64 pack2_(float lo, float hi) {
    u64 r; asm("mov.b64 %0, {%1, %2};" : "=l"(r) : "f"(lo), "f"(hi)); return r;
}
__device__ __forceinline__ u64 pdup_(float x) {
    u64 r; asm("mov.b64 %0, {%1, %1};" : "=l"(r) : "f"(x)); return r;
}
__device__ __forceinline__ u64 ffma2_(u64 a, u64 b, u64 c) {
    u64 d; asm("fma.rn.f32x2 %0, %1, %2, %3;" : "=l"(d) : "l"(a), "l"(b), "l"(c)); return d;
}
__device__ __forceinline__ u64 mul2_(u64 a, u64 b) {
    u64 d; asm("mul.rn.f32x2 %0, %1, %2;" : "=l"(d) : "l"(a), "l"(b)); return d;
}
__device__ __forceinline__ float2 unpack2_(u64 v) {
    float2 f; asm("mov.b64 {%0, %1}, %2;" : "=f"(f.x), "=f"(f.y) : "l"(v)); return f;
}
__device__ __forceinline__ uint32_t smem_u32_(const void* p) {
    return (uint32_t)__cvta_generic_to_shared(p);
}
__device__ __forceinline__ void cpasync16_(uint32_t dst, const void* src, int srcbytes) {
    asm volatile("cp.async.ca.shared.global [%0], [%1], 16, %2;"
                 :: "r"(dst), "l"(src), "r"(srcbytes));
}
__device__ __forceinline__ void split2_(float v0, float v1,
                                        __nv_bfloat16* hi, __nv_bfloat16* lo, size_t off) {
    __nv_bfloat16 h0 = __float2bfloat16(v0);
    __nv_bfloat16 h1 = __float2bfloat16(v1);
    __nv_bfloat162 hp; hp.x = h0; hp.y = h1;
    __nv_bfloat162 lp;
    lp.x = __float2bfloat16(v0 - __bfloat162float(h0));
    lp.y = __float2bfloat16(v1 - __bfloat162float(h1));
    *(__nv_bfloat162*)(hi + off) = hp;
    *(__nv_bfloat162*)(lo + off) = lp;
}

// ---------------- hi/lo split into bf16 ----------------
__global__ void split_kernel(const float* __restrict__ x, __nv_bfloat16* __restrict__ hi,
                             __nv_bfloat16* __restrict__ lo, int n)
{
    int i = blockIdx.x * 256 + threadIdx.x;
    if (i < n) {
        float a = x[i];
        __nv_bfloat16 h = __float2bfloat16(a);
        hi[i] = h;
        lo[i] = __float2bfloat16(a - __bfloat162float(h));
    }
}

// ---------------- bf16 mma.sync NT GEMM (3-term compensated) ----------------
enum { EPI_NONE = 0, EPI_DSWISH = 1, EPI_RES = 2 };
#define SSTRIDE 40

template <int EPI, int WC, int WS>
__global__ void __launch_bounds__(256)
gemm_mma_kernel(const __nv_bfloat16* __restrict__ Ahi, const __nv_bfloat16* __restrict__ Alo,
                const __nv_bfloat16* __restrict__ Bhi, const __nv_bfloat16* __restrict__ Blo,
                const float* __restrict__ bias, const float* __restrict__ res,
                float* __restrict__ C,
                __nv_bfloat16* __restrict__ Ohi, __nv_bfloat16* __restrict__ Olo,
                int M, int N, int K)
{
    __shared__ __nv_bfloat16 smA[2][128 * SSTRIDE];
    __shared__ __nv_bfloat16 smB[2][128 * SSTRIDE];

    const int tid = threadIdx.x;
    const int wid = tid >> 5;
    const int lane = tid & 31;
    const int m0 = blockIdx.y * 128, n0 = blockIdx.x * 128;
    const int nk = K >> 5;
    const int NI = 3 * nk;

    const int mw = (wid & 1) * 64;
    const int nw = (wid >> 1) * 32;

    float acc[4][4][4];
#pragma unroll
    for (int a = 0; a < 4; a++)
#pragma unroll
        for (int b = 0; b < 4; b++)
#pragma unroll
            for (int c = 0; c < 4; c++) acc[a][b][c] = 0.f;

    const int lrow0 = tid >> 2,         lc0 = (tid & 3) << 3;
    const int lrow1 = (tid + 256) >> 2, lc1 = ((tid + 256) & 3) << 3;
    const uint32_t smA_u = smem_u32_(smA);
    const uint32_t smB_u = smem_u32_(smB);
    const uint32_t adst0 = smA_u + (uint32_t)(lrow0 * SSTRIDE + lc0) * 2;
    const uint32_t adst1 = smA_u + (uint32_t)(lrow1 * SSTRIDE + lc1) * 2;
    const uint32_t bdst0 = smB_u + (uint32_t)(lrow0 * SSTRIDE + lc0) * 2;
    const uint32_t bdst1 = smB_u + (uint32_t)(lrow1 * SSTRIDE + lc1) * 2;
    const int am0 = m0 + lrow0, am1 = m0 + lrow1;
    const int stage_b = 128 * SSTRIDE * 2;

    auto issue_loads = [&](int kt) {
        int pass = (kt >= 2 * nk) ? 2 : ((kt >= nk) ? 1 : 0);
        int kk0 = (kt - pass * nk) << 5;
        const __nv_bfloat16* Asrc = (pass == 1) ? Alo : Ahi;
        const __nv_bfloat16* Bsrc = (pass == 2) ? Blo : Bhi;
        uint32_t so = (kt & 1) * stage_b;
        cpasync16_(adst0 + so, Asrc + (size_t)(am0 < M ? am0 : 0) * K + kk0 + lc0, am0 < M ? 16 : 0);
        cpasync16_(adst1 + so, Asrc + (size_t)(am1 < M ? am1 : 0) * K + kk0 + lc1, am1 < M ? 16 : 0);
        cpasync16_(bdst0 + so, Bsrc + (size_t)(n0 + lrow0) * K + kk0 + lc0, 16);
        cpasync16_(bdst1 + so, Bsrc + (size_t)(n0 + lrow1) * K + kk0 + lc1, 16);
    };

    issue_loads(0);
    asm volatile("cp.async.commit_group;" ::: "memory");

    const int lr8 = lane & 7;
    const int sel = lane >> 3;

    for (int kt = 0; kt < NI; kt++) {
        if (kt + 1 < NI) issue_loads(kt + 1);
        asm volatile("cp.async.commit_group;" ::: "memory");
        asm volatile("cp.async.wait_group 1;" ::: "memory");
        __syncthreads();

        const uint32_t aBase = smA_u + (kt & 1) * stage_b;
        const uint32_t bBase = smB_u + (kt & 1) * stage_b;
#pragma unroll
        for (int kk = 0; kk < 2; kk++) {
            uint32_t a[4][4];
#pragma unroll
            for (int mt = 0; mt < 4; mt++) {
                int row = mw + mt * 16 + lr8 + (sel & 1) * 8;
                int col = kk * 16 + (sel >> 1) * 8;
                uint32_t addr = aBase + (uint32_t)(row * SSTRIDE + col) * 2;
                asm volatile("ldmatrix.sync.aligned.m8n8.x4.shared.b16 {%0,%1,%2,%3}, [%4];"
                             : "=r"(a[mt][0]), "=r"(a[mt][1]), "=r"(a[mt][2]), "=r"(a[mt][3])
                             : "r"(addr));
            }
            uint32_t bfr[2][4];
#pragma unroll
            for (int np = 0; np < 2; np++) {
                int row = nw + np * 16 + lr8 + (sel >> 1) * 8;
                int col = kk * 16 + (sel & 1) * 8;
                uint32_t addr = bBase + (uint32_t)(row * SSTRIDE + col) * 2;
                asm volatile("ldmatrix.sync.aligned.m8n8.x4.shared.b16 {%0,%1,%2,%3}, [%4];"
                             : "=r"(bfr[np][0]), "=r"(bfr[np][1]), "=r"(bfr[np][2]), "=r"(bfr[np][3])
                             : "r"(addr));
            }
#pragma unroll
            for (int mt = 0; mt < 4; mt++) {
#pragma unroll
                for (int nt = 0; nt < 4; nt++) {
                    uint32_t b0 = bfr[nt >> 1][(nt & 1) * 2 + 0];
                    uint32_t b1 = bfr[nt >> 1][(nt & 1) * 2 + 1];
                    asm volatile(
                        "mma.sync.aligned.m16n8k16.row.col.f32.bf16.bf16.f32 "
                        "{%0,%1,%2,%3}, {%4,%5,%6,%7}, {%8,%9}, {%0,%1,%2,%3};"
                        : "+f"(acc[mt][nt][0]), "+f"(acc[mt][nt][1]),
                          "+f"(acc[mt][nt][2]), "+f"(acc[mt][nt][3])
                        : "r"(a[mt][0]), "r"(a[mt][1]), "r"(a[mt][2]), "r"(a[mt][3]),
                          "r"(b0), "r"(b1));
                }
            }
        }
        __syncthreads();
    }

    const int g = lane >> 2, t4 = lane & 3;
#pragma unroll
    for (int mt = 0; mt < 4; mt++) {
#pragma unroll
        for (int rr = 0; rr < 2; rr++) {
            int row = m0 + mw + mt * 16 + g + rr * 8;
            if (row >= M) continue;
#pragma unroll
            for (int nt = 0; nt < 4; nt++) {
                int col = n0 + nw + nt * 8 + t4 * 2;
                float v0 = acc[mt][nt][rr * 2 + 0];
                float v1 = acc[mt][nt][rr * 2 + 1];
                if (bias) { v0 += bias[col]; v1 += bias[col + 1]; }
                if (EPI == EPI_DSWISH) {
                    v0 = v0 * sigmoidf_(v0 - 1.f);
                    v1 = v1 * sigmoidf_(v1 - 1.f);
                }
                size_t off = (size_t)row * N + col;
                if (EPI == EPI_RES) {
                    float2 rv = *(const float2*)&res[off];
                    v0 += rv.x; v1 += rv.y;
                }
                if (WC) *(float2*)&C[off] = make_float2(v0, v1);
                if (WS) split2_(v0, v1, Ohi, Olo, off);
            }
        }
    }
}

// ---------------- fused attention: scores + rel_shift + online softmax + AV ----------------
// Block = (bh, 64-row i-tile). Output ctx (split bf16) in (T,B,E) layout.
#define ATTN_SMEM ((64 * 65 + 64 + 64 * 65 + 64 * 128 + 64 * 68 + 64 * 68) * 4)

__global__ void __launch_bounds__(256)
attn_fused_kernel(const float* __restrict__ qkv,
                  const float* __restrict__ pproj,
                  const float* __restrict__ u,
                  const float* __restrict__ v,
                  __nv_bfloat16* __restrict__ chi,
                  __nv_bfloat16* __restrict__ clo)
{
    extern __shared__ float sm[];
    float* Qu  = sm;                    // [64][65]
    float* duv = Qu + 64 * 65;          // [64]
    float* Kt  = duv + 64;              // [64][65]
    float* Ps  = Kt + 64 * 65;          // [64][128]
    float* Vs  = Ps + 64 * 128;         // [64][68]
    float* Es  = Vs + 64 * 68;          // [64][68]

    const int bh = blockIdx.y;
    const int b = bh >> 3, h = bh & 7;
    const int i0 = blockIdx.x * 64;
    const int tid = threadIdx.x;
    const float scale = 0.125f;

    for (int idx = tid; idx < 64 * 64; idx += 256) {
        int li = idx >> 6, d = idx & 63;
        float q = qkv[(size_t)((i0 + li) * B_ + b) * (3 * E_) + h * 64 + d] * scale;
        Qu[li * 65 + d] = q + u[h * 64 + d];
    }
    if (tid < 64) duv[tid] = v[h * 64 + tid] - u[h * 64 + tid];

    const int tm = (tid >> 4) << 2;
    const int tn = (tid & 15) << 2;
    const int base = 63 - tm + tn;

    float mrow[4], lrow[4];
#pragma unroll
    for (int i = 0; i < 4; i++) { mrow[i] = -1e30f; lrow[i] = 0.f; }
    u64 outacc[4][2];
#pragma unroll
    for (int i = 0; i < 4; i++) { outacc[i][0] = 0ull; outacc[i][1] = 0ull; }

    for (int j0 = 0; j0 < T_; j0 += 64) {
        __syncthreads();    // previous iteration's Kt/Vs/Ps/Es reads done
        for (int idx = tid; idx < 64 * 64; idx += 256) {
            int li = idx >> 6, d = idx & 63;
            size_t rb = (size_t)((j0 + li) * B_ + b) * (3 * E_) + h * 64 + d;
            Kt[li * 65 + d] = qkv[rb + E_];
            Vs[li * 68 + d] = qkv[rb + 2 * E_];
        }
        const int m_min = 960 - i0 + j0;
        for (int idx = tid; idx < 64 * 127; idx += 256) {
            int d = idx / 127, mm = idx % 127;
            Ps[d * 128 + mm] = pproj[(size_t)(m_min + mm) * E_ + h * 64 + d];
        }
        __syncthreads();

        // ---- score tile ----
        u64 acc2[4][2];
#pragma unroll
        for (int i = 0; i < 4; i++) { acc2[i][0] = 0ull; acc2[i][1] = 0ull; }

#pragma unroll 4
        for (int d = 0; d < 64; d++) {
            float duvd = duv[d];
            u64 ad[4], cd[4];
#pragma unroll
            for (int ii = 0; ii < 4; ii++) {
                float qu = Qu[(tm + ii) * 65 + d];
                ad[ii] = pdup_(qu);
                cd[ii] = pdup_(qu + duvd);
            }
            float bb0 = Kt[(tn + 0) * 65 + d], bb1 = Kt[(tn + 1) * 65 + d];
            float bb2 = Kt[(tn + 2) * 65 + d], bb3 = Kt[(tn + 3) * 65 + d];
            u64 kb0 = pack2_(bb0, bb1), kb1 = pack2_(bb2, bb3);
            float p7[7];
#pragma unroll
            for (int t = 0; t < 7; t++) p7[t] = Ps[d * 128 + base + t - 3];
            u64 pp[6];
#pragma unroll
            for (int t = 0; t < 6; t++) pp[t] = pack2_(p7[t], p7[t + 1]);
#pragma unroll
            for (int ii = 0; ii < 4; ii++) {
                acc2[ii][0] = ffma2_(ad[ii], kb0, acc2[ii][0]);
                acc2[ii][1] = ffma2_(ad[ii], kb1, acc2[ii][1]);
                acc2[ii][0] = ffma2_(cd[ii], pp[3 - ii], acc2[ii][0]);
                acc2[ii][1] = ffma2_(cd[ii], pp[5 - ii], acc2[ii][1]);
            }
        }

        // ---- online softmax update ----
#pragma unroll
        for (int ii = 0; ii < 4; ii++) {
            float2 t0 = unpack2_(acc2[ii][0]);
            float2 t1 = unpack2_(acc2[ii][1]);
            float s0 = t0.x, s1 = t0.y, s2 = t1.x, s3 = t1.y;
            float mx = fmaxf(fmaxf(s0, s1), fmaxf(s2, s3));
#pragma unroll
            for (int o = 1; o < 16; o <<= 1)
                mx = fmaxf(mx, __shfl_xor_sync(0xffffffffu, mx, o));
            float mnew = fmaxf(mrow[ii], mx);
            float alpha = __expf(mrow[ii] - mnew);
            mrow[ii] = mnew;
            s0 = __expf(s0 - mnew); s1 = __expf(s1 - mnew);
            s2 = __expf(s2 - mnew); s3 = __expf(s3 - mnew);
            float rs = s0 + s1 + s2 + s3;
#pragma unroll
            for (int o = 1; o < 16; o <<= 1)
                rs += __shfl_xor_sync(0xffffffffu, rs, o);
            lrow[ii] = lrow[ii] * alpha + rs;
            u64 al = pdup_(alpha);
            outacc[ii][0] = mul2_(outacc[ii][0], al);
            outacc[ii][1] = mul2_(outacc[ii][1], al);
            *(float4*)&Es[(tm + ii) * 68 + tn] = make_float4(s0, s1, s2, s3);
        }
        __syncthreads();

        // ---- AV accumulate ----
#pragma unroll 8
        for (int kk = 0; kk < 64; kk++) {
            ulonglong2 bq = *(const ulonglong2*)&Vs[kk * 68 + tn];
#pragma unroll
            for (int ii = 0; ii < 4; ii++) {
                u64 a = pdup_(Es[(tm + ii) * 68 + kk]);
                outacc[ii][0] = ffma2_(a, bq.x, outacc[ii][0]);
                outacc[ii][1] = ffma2_(a, bq.y, outacc[ii][1]);
            }
        }
    }

    // ---- epilogue ----
#pragma unroll
    for (int ii = 0; ii < 4; ii++) {
        float inv = 1.f / lrow[ii];
        float2 t0 = unpack2_(outacc[ii][0]);
        float2 t1 = unpack2_(outacc[ii][1]);
        size_t off = (size_t)((i0 + tm + ii) * B_ + b) * E_ + h * 64 + tn;
        split2_(t0.x * inv, t0.y * inv, chi, clo, off);
        split2_(t1.x * inv, t1.y * inv, chi, clo, off + 2);
    }
}

// ---------------- GLU ----------------
__global__ void glu_kernel(const float* __restrict__ y, float* __restrict__ out)
{
    int idx = blockIdx.x * 256 + threadIdx.x;
    if (idx >= NTOK * E_) return;
    int r = idx >> 9, c = idx & 511;
    float a = y[(size_t)r * 1024 + c];
    float g = y[(size_t)r * 1024 + 512 + c];
    out[idx] = a * sigmoidf_(g);
}

// ---------------- depthwise conv + DoubleSwish -> split bf16 ----------------
__global__ void dwconv_kernel(const float* __restrict__ x, const float* __restrict__ w,
                              const float* __restrict__ bias,
                              __nv_bfloat16* __restrict__ ohi, __nv_bfloat16* __restrict__ olo)
{
    int idx = blockIdx.x * 256 + threadIdx.x;
    if (idx >= NTOK * E_) return;
    int c = idx & 511;
    int tb = idx >> 9;
    int t = tb >> 2, b = tb & 3;
    float acc = bias[c];
#pragma unroll
    for (int k = 0; k < KCONV; k++) {
        int tt = t + k - 15;
        if (tt >= 0 && tt < T_)
            acc += x[(size_t)(tt * B_ + b) * E_ + c] * w[c * KCONV + k];
    }
    float vv = acc * sigmoidf_(acc - 1.f);
    __nv_bfloat16 h = __float2bfloat16(vv);
    ohi[idx] = h;
    olo[idx] = __float2bfloat16(vv - __bfloat162float(h));
}

// ---------------- BasicNorm ----------------
__global__ void basic_norm_kernel(const float* __restrict__ x, const float* __restrict__ leps,
                                  float* __restrict__ out)
{
    __shared__ float red[8];
    const int tid = threadIdx.x;
    const float* p = x + (size_t)blockIdx.x * E_;
    float v0 = p[tid], v1 = p[tid + 256];
    float ss = v0 * v0 + v1 * v1;
#pragma unroll
    for (int o = 16; o > 0; o >>= 1) ss += __shfl_xor_sync(0xffffffffu, ss, o);
    if ((tid & 31) == 0) red[tid >> 5] = ss;
    __syncthreads();
    float tot = red[0];
#pragma unroll
    for (int i = 1; i < 8; i++) tot += red[i];
    float r = rsqrtf(tot * (1.f / (float)E_) + __expf(leps[0]));
    out[(size_t)blockIdx.x * E_ + tid]       = v0 * r;
    out[(size_t)blockIdx.x * E_ + tid + 256] = v1 * r;
}

// ---------------- launch ----------------
extern "C" void kernel_launch(void* const* d_in, const int* in_sizes, int n_in,
                              void* d_out, int out_size)
{
    const float* src      = (const float*)d_in[0];
    const float* pos_emb  = (const float*)d_in[1];
    const float* in_w     = (const float*)d_in[2];
    const float* in_b     = (const float*)d_in[3];
    const float* out_w    = (const float*)d_in[4];
    const float* out_b    = (const float*)d_in[5];
    const float* wpos     = (const float*)d_in[6];
    const float* u        = (const float*)d_in[7];
    const float* v        = (const float*)d_in[8];
    const float* ffm_w1   = (const float*)d_in[9];
    const float* ffm_b1   = (const float*)d_in[10];
    const float* ffm_w2   = (const float*)d_in[11];
    const float* ffm_b2   = (const float*)d_in[12];
    const float* ff_w1    = (const float*)d_in[13];
    const float* ff_b1    = (const float*)d_in[14];
    const float* ff_w2    = (const float*)d_in[15];
    const float* ff_b2    = (const float*)d_in[16];
    const float* pw1_w    = (const float*)d_in[17];
    const float* pw1_b    = (const float*)d_in[18];
    const float* dw_w     = (const float*)d_in[19];
    const float* dw_b     = (const float*)d_in[20];
    const float* pw2_w    = (const float*)d_in[21];
    const float* pw2_b    = (const float*)d_in[22];
    const float* leps     = (const float*)d_in[23];

    float *ff, *x1, *x2, *x3, *qkv, *pp, *glu;
    __nv_bfloat16 *whi, *wlo, *ahi, *alo, *bhi, *blo;
    cudaGetSymbolAddress((void**)&ff,  g_ff);
    cudaGetSymbolAddress((void**)&x1,  g_x1);
    cudaGetSymbolAddress((void**)&x2,  g_x2);
    cudaGetSymbolAddress((void**)&x3,  g_x3);
    cudaGetSymbolAddress((void**)&qkv, g_qkv);
    cudaGetSymbolAddress((void**)&pp,  g_pproj);
    cudaGetSymbolAddress((void**)&glu, g_glu);
    cudaGetSymbolAddress((void**)&whi, g_whi);
    cudaGetSymbolAddress((void**)&wlo, g_wlo);
    cudaGetSymbolAddress((void**)&ahi, g_ahi);
    cudaGetSymbolAddress((void**)&alo, g_alo);
    cudaGetSymbolAddress((void**)&bhi, g_bhi);
    cudaGetSymbolAddress((void**)&blo, g_blo);

    cudaFuncSetAttribute(attn_fused_kernel, cudaFuncAttributeMaxDynamicSharedMemorySize,
                         ATTN_SMEM);

    auto split = [&](const float* x, __nv_bfloat16* h, __nv_bfloat16* l, int n) {
        split_kernel<<<(n + 255) / 256, 256>>>(x, h, l, n);
    };

    // 0) split weights + pos_emb once
    split(ffm_w1,  whi + OFF_FFM_W1, wlo + OFF_FFM_W1, DFF_ * E_);
    split(ffm_w2,  whi + OFF_FFM_W2, wlo + OFF_FFM_W2, E_ * DFF_);
    split(in_w,    whi + OFF_IN_W,   wlo + OFF_IN_W,   3 * E_ * E_);
    split(wpos,    whi + OFF_WPOS,   wlo + OFF_WPOS,   E_ * E_);
    split(out_w,   whi + OFF_OUT_W,  wlo + OFF_OUT_W,  E_ * E_);
    split(pw1_w,   whi + OFF_PW1_W,  wlo + OFF_PW1_W,  2 * E_ * E_);
    split(pw2_w,   whi + OFF_PW2_W,  wlo + OFF_PW2_W,  E_ * E_);
    split(ff_w1,   whi + OFF_FF_W1,  wlo + OFF_FF_W1,  DFF_ * E_);
    split(ff_w2,   whi + OFF_FF_W2,  wlo + OFF_FF_W2,  E_ * DFF_);
    split(pos_emb, whi + OFF_POSE,   wlo + OFF_POSE,   PLEN * E_);

    // 1) macaron FFN
    split(src, ahi, alo, NTOK * E_);
    gemm_mma_kernel<EPI_DSWISH, 0, 1><<<dim3(DFF_ / 128, NTOK / 128), 256>>>(
        ahi, alo, whi + OFF_FFM_W1, wlo + OFF_FFM_W1, ffm_b1, nullptr,
        nullptr, bhi, blo, NTOK, DFF_, E_);
    gemm_mma_kernel<EPI_RES, 1, 1><<<dim3(E_ / 128, NTOK / 128), 256>>>(
        bhi, blo, whi + OFF_FFM_W2, wlo + OFF_FFM_W2, ffm_b2, src,
        x1, ahi, alo, NTOK, E_, DFF_);

    // 2) attention
    gemm_mma_kernel<EPI_NONE, 1, 0><<<dim3((3 * E_) / 128, NTOK / 128), 256>>>(
        ahi, alo, whi + OFF_IN_W, wlo + OFF_IN_W, in_b, nullptr,
        qkv, nullptr, nullptr, NTOK, 3 * E_, E_);
    gemm_mma_kernel<EPI_NONE, 1, 0><<<dim3(E_ / 128, (PLEN + 127) / 128), 256>>>(
        whi + OFF_POSE, wlo + OFF_POSE, whi + OFF_WPOS, wlo + OFF_WPOS, nullptr, nullptr,
        pp, nullptr, nullptr, PLEN, E_, E_);
    attn_fused_kernel<<<dim3(T_ / 64, B_ * H_), 256, ATTN_SMEM>>>(qkv, pp, u, v, bhi, blo);
    gemm_mma_kernel<EPI_RES, 1, 1><<<dim3(E_ / 128, NTOK / 128), 256>>>(
        bhi, blo, whi + OFF_OUT_W, wlo + OFF_OUT_W, out_b, x1,
        x2, ahi, alo, NTOK, E_, E_);

    // 3) conv module
    gemm_mma_kernel<EPI_NONE, 1, 0><<<dim3((2 * E_) / 128, NTOK / 128), 256>>>(
        ahi, alo, whi + OFF_PW1_W, wlo + OFF_PW1_W, pw1_b, nullptr,
        ff, nullptr, nullptr, NTOK, 2 * E_, E_);
    glu_kernel<<<(NTOK * E_) / 256, 256>>>(ff, glu);
    dwconv_kernel<<<(NTOK * E_) / 256, 256>>>(glu, dw_w, dw_b, bhi, blo);
    gemm_mma_kernel<EPI_RES, 1, 1><<<dim3(E_ / 128, NTOK / 128), 256>>>(
        bhi, blo, whi + OFF_PW2_W, wlo + OFF_PW2_W, pw2_b, x2,
        x3, ahi, alo, NTOK, E_, E_);

    // 4) second FFN
    gemm_mma_kernel<EPI_DSWISH, 0, 1><<<dim3(DFF_ / 128, NTOK / 128), 256>>>(
        ahi, alo, whi + OFF_FF_W1, wlo + OFF_FF_W1, ff_b1, nullptr,
        nullptr, bhi, blo, NTOK, DFF_, E_);
    gemm_mma_kernel<EPI_RES, 1, 0><<<dim3(E_ / 128, NTOK / 128), 256>>>(
        bhi, blo, whi + OFF_FF_W2, wlo + OFF_FF_W2, ff_b2, x3,
        x1, nullptr, nullptr, NTOK, E_, DFF_);

    // 5) BasicNorm -> output
    basic_norm_kernel<<<NTOK, 256>>>(x1, leps, (float*)d_out);
}

// round 8
// speedup vs baseline: 1.8736x; 1.1145x over previous
#include <cuda_runtime.h>
#include <cuda_bf16.h>
#include <math.h>
#include <stdint.h>

// ---------------- problem dims ----------------
#define T_    1024
#define B_    4
#define E_    512
#define H_    8
#define D_    64
#define DFF_  2048
#define NTOK  4096
#define PLEN  2047
#define KCONV 31

typedef unsigned long long u64;

// ---------------- scratch ----------------
__device__ float g_ff[NTOK * DFF_];
__device__ float g_x1[NTOK * E_];
__device__ float g_x2[NTOK * E_];
__device__ float g_x3[NTOK * E_];
__device__ float g_qkv[NTOK * 3 * E_];
__device__ float g_pproj[PLEN * E_];
__device__ float g_glu[NTOK * E_];
__device__ __nv_bfloat16 g_whi[7339520];
__device__ __nv_bfloat16 g_wlo[7339520];
__device__ __nv_bfloat16 g_ahi[NTOK * DFF_];
__device__ __nv_bfloat16 g_alo[NTOK * DFF_];
__device__ __nv_bfloat16 g_bhi[NTOK * DFF_];
__device__ __nv_bfloat16 g_blo[NTOK * DFF_];

// packed weight offsets (elements)
#define OFF_FFM_W1 0
#define OFF_FFM_W2 1048576
#define OFF_IN_W   2097152
#define OFF_WPOS   2883584
#define OFF_OUT_W  3145728
#define OFF_PW1_W  3407872
#define OFF_PW2_W  3932160
#define OFF_FF_W1  4194304
#define OFF_FF_W2  5242880
#define OFF_POSE   6291456

__device__ __forceinline__ float sigmoidf_(float x) { return 1.f / (1.f + __expf(-x)); }

// ---------------- packed f32x2 helpers ----------------
__device__ __forceinline__ u64 pack2_(float lo, float hi) {
    u64 r; asm("mov.b64 %0, {%1, %2};" : "=l"(r) : "f"(lo), "f"(hi)); return r;
}
__device__ __forceinline__ u64 pdup_(float x) {
    u64 r; asm("mov.b64 %0, {%1, %1};" : "=l"(r) : "f"(x)); return r;
}
__device__ __forceinline__ u64 ffma2_(u64 a, u64 b, u64 c) {
    u64 d; asm("fma.rn.f32x2 %0, %1, %2, %3;" : "=l"(d) : "l"(a), "l"(b), "l"(c)); return d;
}
__device__ __forceinline__ u64 mul2_(u64 a, u64 b) {
    u64 d; asm("mul.rn.f32x2 %0, %1, %2;" : "=l"(d) : "l"(a), "l"(b)); return d;
}
__device__ __forceinline__ float2 unpack2_(u64 v) {
    float2 f; asm("mov.b64 {%0, %1}, %2;" : "=f"(f.x), "=f"(f.y) : "l"(v)); return f;
}
__device__ __forceinline__ uint32_t smem_u32_(const void* p) {
    return (uint32_t)__cvta_generic_to_shared(p);
}
__device__ __forceinline__ void cpasync16_(uint32_t dst, const void* src, int srcbytes) {
    asm volatile("cp.async.ca.shared.global [%0], [%1], 16, %2;"
                 :: "r"(dst), "l"(src), "r"(srcbytes));
}
__device__ __forceinline__ void split2_(float v0, float v1,
                                        __nv_bfloat16* hi, __nv_bfloat16* lo, size_t off) {
    __nv_bfloat16 h0 = __float2bfloat16(v0);
    __nv_bfloat16 h1 = __float2bfloat16(v1);
    __nv_bfloat162 hp; hp.x = h0; hp.y = h1;
    __nv_bfloat162 lp;
    lp.x = __float2bfloat16(v0 - __bfloat162float(h0));
    lp.y = __float2bfloat16(v1 - __bfloat162float(h1));
    *(__nv_bfloat162*)(hi + off) = hp;
    *(__nv_bfloat162*)(lo + off) = lp;
}

// ---------------- hi/lo split into bf16 ----------------
__global__ void split_kernel(const float* __restrict__ x, __nv_bfloat16* __restrict__ hi,
                             __nv_bfloat16* __restrict__ lo, int n)
{
    int i = blockIdx.x * 256 + threadIdx.x;
    if (i < n) {
        float a = x[i];
        __nv_bfloat16 h = __float2bfloat16(a);
        hi[i] = h;
        lo[i] = __float2bfloat16(a - __bfloat162float(h));
    }
}

// ---------------- bf16 mma.sync NT GEMM, fused 3-term K loop ----------------
// C(MxN) = epi( A(MxK) * B(NxK)^T + bias ); acc = Ahi*Bhi + Alo*Bhi + Ahi*Blo (fp32).
enum { EPI_NONE = 0, EPI_DSWISH = 1, EPI_RES = 2 };
#define SSTRIDE 40
#define TILE_E  (128 * SSTRIDE)          // bf16 elems per tile
#define STAGE_E (4 * TILE_E)             // Ahi, Alo, Bhi, Blo
#define GEMM_SMEM_B (2 * STAGE_E * 2)    // 81920 bytes

template <int EPI, int WC, int WS>
__global__ void __launch_bounds__(256)
gemm_mma_kernel(const __nv_bfloat16* __restrict__ Ahi, const __nv_bfloat16* __restrict__ Alo,
                const __nv_bfloat16* __restrict__ Bhi, const __nv_bfloat16* __restrict__ Blo,
                const float* __restrict__ bias, const float* __restrict__ res,
                float* __restrict__ C,
                __nv_bfloat16* __restrict__ Ohi, __nv_bfloat16* __restrict__ Olo,
                int M, int N, int K)
{
    extern __shared__ __nv_bfloat16 smem_g[];

    const int tid = threadIdx.x;
    const int wid = tid >> 5;
    const int lane = tid & 31;
    const int m0 = blockIdx.y * 128, n0 = blockIdx.x * 128;
    const int nk = K >> 5;

    const int mw = (wid & 1) * 64;
    const int nw = (wid >> 1) * 32;

    float acc[4][4][4];
#pragma unroll
    for (int a = 0; a < 4; a++)
#pragma unroll
        for (int b = 0; b < 4; b++)
#pragma unroll
            for (int c = 0; c < 4; c++) acc[a][b][c] = 0.f;

    // cp.async chunk mapping: 2 chunks of 16B per tile per thread
    const int r0 = tid >> 2,         col0 = (tid & 3) << 3;
    const int r1 = (tid + 256) >> 2, col1 = ((tid + 256) & 3) << 3;
    const uint32_t s_u = smem_u32_(smem_g);
    const uint32_t d0 = (uint32_t)(r0 * SSTRIDE + col0) * 2;
    const uint32_t d1 = (uint32_t)(r1 * SSTRIDE + col1) * 2;
    const int am0 = m0 + r0, am1 = m0 + r1;
    const int asz0 = am0 < M ? 16 : 0;
    const int asz1 = am1 < M ? 16 : 0;
    const size_t arow0 = (size_t)(am0 < M ? am0 : 0) * K;
    const size_t arow1 = (size_t)(am1 < M ? am1 : 0) * K;
    const size_t brow0 = (size_t)(n0 + r0) * K;
    const size_t brow1 = (size_t)(n0 + r1) * K;

    auto issue_loads = [&](int kt) {
        int kk0 = kt << 5;
        uint32_t so = (kt & 1) ? (uint32_t)STAGE_E * 2 : 0u;
        // Ahi (tile 0)
        cpasync16_(s_u + so + d0, Ahi + arow0 + kk0 + col0, asz0);
        cpasync16_(s_u + so + d1, Ahi + arow1 + kk0 + col1, asz1);
        // Alo (tile 1)
        cpasync16_(s_u + so + TILE_E * 2 + d0, Alo + arow0 + kk0 + col0, asz0);
        cpasync16_(s_u + so + TILE_E * 2 + d1, Alo + arow1 + kk0 + col1, asz1);
        // Bhi (tile 2)
        cpasync16_(s_u + so + 2 * TILE_E * 2 + d0, Bhi + brow0 + kk0 + col0, 16);
        cpasync16_(s_u + so + 2 * TILE_E * 2 + d1, Bhi + brow1 + kk0 + col1, 16);
        // Blo (tile 3)
        cpasync16_(s_u + so + 3 * TILE_E * 2 + d0, Blo + brow0 + kk0 + col0, 16);
        cpasync16_(s_u + so + 3 * TILE_E * 2 + d1, Blo + brow1 + kk0 + col1, 16);
    };

    issue_loads(0);
    asm volatile("cp.async.commit_group;" ::: "memory");

    const int lr8 = lane & 7;
    const int sel = lane >> 3;

    for (int kt = 0; kt < nk; kt++) {
        if (kt + 1 < nk) issue_loads(kt + 1);
        asm volatile("cp.async.commit_group;" ::: "memory");
        asm volatile("cp.async.wait_group 1;" ::: "memory");
        __syncthreads();

        const uint32_t base = s_u + ((kt & 1) ? (uint32_t)STAGE_E * 2 : 0u);
#pragma unroll
        for (int kk = 0; kk < 2; kk++) {
            uint32_t ahi[4][4], alo[4][4];
#pragma unroll
            for (int mt = 0; mt < 4; mt++) {
                int row = mw + mt * 16 + lr8 + (sel & 1) * 8;
                int col = kk * 16 + (sel >> 1) * 8;
                uint32_t addr = base + (uint32_t)(row * SSTRIDE + col) * 2;
                asm volatile("ldmatrix.sync.aligned.m8n8.x4.shared.b16 {%0,%1,%2,%3}, [%4];"
                             : "=r"(ahi[mt][0]), "=r"(ahi[mt][1]), "=r"(ahi[mt][2]), "=r"(ahi[mt][3])
                             : "r"(addr));
                asm volatile("ldmatrix.sync.aligned.m8n8.x4.shared.b16 {%0,%1,%2,%3}, [%4];"
                             : "=r"(alo[mt][0]), "=r"(alo[mt][1]), "=r"(alo[mt][2]), "=r"(alo[mt][3])
                             : "r"(addr + TILE_E * 2));
            }
            uint32_t bhi[2][4], blo[2][4];
#pragma unroll
            for (int np = 0; np < 2; np++) {
                int row = nw + np * 16 + lr8 + (sel >> 1) * 8;
                int col = kk * 16 + (sel & 1) * 8;
                uint32_t addr = base + 2 * TILE_E * 2 + (uint32_t)(row * SSTRIDE + col) * 2;
                asm volatile("ldmatrix.sync.aligned.m8n8.x4.shared.b16 {%0,%1,%2,%3}, [%4];"
                             : "=r"(bhi[np][0]), "=r"(bhi[np][1]), "=r"(bhi[np][2]), "=r"(bhi[np][3])
                             : "r"(addr));
                asm volatile("ldmatrix.sync.aligned.m8n8.x4.shared.b16 {%0,%1,%2,%3}, [%4];"
                             : "=r"(blo[np][0]), "=r"(blo[np][1]), "=r"(blo[np][2]), "=r"(blo[np][3])
                             : "r"(addr + TILE_E * 2));
            }
#define MMA_(AH, BH)                                                            \
            _Pragma("unroll")                                                   \
            for (int mt = 0; mt < 4; mt++) {                                    \
                _Pragma("unroll")                                               \
                for (int nt = 0; nt < 4; nt++) {                                \
                    uint32_t b0 = BH[nt >> 1][(nt & 1) * 2 + 0];                \
                    uint32_t b1 = BH[nt >> 1][(nt & 1) * 2 + 1];                \
                    asm volatile(                                               \
                        "mma.sync.aligned.m16n8k16.row.col.f32.bf16.bf16.f32 "  \
                        "{%0,%1,%2,%3}, {%4,%5,%6,%7}, {%8,%9}, {%0,%1,%2,%3};" \
                        : "+f"(acc[mt][nt][0]), "+f"(acc[mt][nt][1]),           \
                          "+f"(acc[mt][nt][2]), "+f"(acc[mt][nt][3])            \
                        : "r"(AH[mt][0]), "r"(AH[mt][1]),                       \
                          "r"(AH[mt][2]), "r"(AH[mt][3]),                       \
                          "r"(b0), "r"(b1));                                    \
                }                                                               \
            }
            MMA_(ahi, bhi)
            MMA_(alo, bhi)
            MMA_(ahi, blo)
#undef MMA_
        }
        __syncthreads();
    }

    const int g = lane >> 2, t4 = lane & 3;
#pragma unroll
    for (int mt = 0; mt < 4; mt++) {
#pragma unroll
        for (int rr = 0; rr < 2; rr++) {
            int row = m0 + mw + mt * 16 + g + rr * 8;
            if (row >= M) continue;
#pragma unroll
            for (int nt = 0; nt < 4; nt++) {
                int col = n0 + nw + nt * 8 + t4 * 2;
                float v0 = acc[mt][nt][rr * 2 + 0];
                float v1 = acc[mt][nt][rr * 2 + 1];
                if (bias) { v0 += bias[col]; v1 += bias[col + 1]; }
                if (EPI == EPI_DSWISH) {
                    v0 = v0 * sigmoidf_(v0 - 1.f);
                    v1 = v1 * sigmoidf_(v1 - 1.f);
                }
                size_t off = (size_t)row * N + col;
                if (EPI == EPI_RES) {
                    float2 rv = *(const float2*)&res[off];
                    v0 += rv.x; v1 += rv.y;
                }
                if (WC) *(float2*)&C[off] = make_float2(v0, v1);
                if (WS) split2_(v0, v1, Ohi, Olo, off);
            }
        }
    }
}

// ---------------- fused attention ----------------
#define ATTN_SMEM ((64 * 65 + 64 + 64 * 65 + 64 * 128 + 64 * 68 + 64 * 68) * 4)

__global__ void __launch_bounds__(256)
attn_fused_kernel(const float* __restrict__ qkv,
                  const float* __restrict__ pproj,
                  const float* __restrict__ u,
                  const float* __restrict__ v,
                  __nv_bfloat16* __restrict__ chi,
                  __nv_bfloat16* __restrict__ clo)
{
    extern __shared__ float sm[];
    float* Qu  = sm;
    float* duv = Qu + 64 * 65;
    float* Kt  = duv + 64;
    float* Ps  = Kt + 64 * 65;
    float* Vs  = Ps + 64 * 128;
    float* Es  = Vs + 64 * 68;

    const int bh = blockIdx.y;
    const int b = bh >> 3, h = bh & 7;
    const int i0 = blockIdx.x * 64;
    const int tid = threadIdx.x;
    const float scale = 0.125f;

    for (int idx = tid; idx < 64 * 64; idx += 256) {
        int li = idx >> 6, d = idx & 63;
        float q = qkv[(size_t)((i0 + li) * B_ + b) * (3 * E_) + h * 64 + d] * scale;
        Qu[li * 65 + d] = q + u[h * 64 + d];
    }
    if (tid < 64) duv[tid] = v[h * 64 + tid] - u[h * 64 + tid];

    const int tm = (tid >> 4) << 2;
    const int tn = (tid & 15) << 2;
    const int base = 63 - tm + tn;

    float mrow[4], lrow[4];
#pragma unroll
    for (int i = 0; i < 4; i++) { mrow[i] = -1e30f; lrow[i] = 0.f; }
    u64 outacc[4][2];
#pragma unroll
    for (int i = 0; i < 4; i++) { outacc[i][0] = 0ull; outacc[i][1] = 0ull; }

    for (int j0 = 0; j0 < T_; j0 += 64) {
        __syncthreads();
        for (int idx = tid; idx < 64 * 64; idx += 256) {
            int li = idx >> 6, d = idx & 63;
            size_t rb = (size_t)((j0 + li) * B_ + b) * (3 * E_) + h * 64 + d;
            Kt[li * 65 + d] = qkv[rb + E_];
            Vs[li * 68 + d] = qkv[rb + 2 * E_];
        }
        const int m_min = 960 - i0 + j0;
        for (int idx = tid; idx < 64 * 127; idx += 256) {
            int d = idx / 127, mm = idx % 127;
            Ps[d * 128 + mm] = pproj[(size_t)(m_min + mm) * E_ + h * 64 + d];
        }
        __syncthreads();

        u64 acc2[4][2];
#pragma unroll
        for (int i = 0; i < 4; i++) { acc2[i][0] = 0ull; acc2[i][1] = 0ull; }

#pragma unroll 4
        for (int d = 0; d < 64; d++) {
            float duvd = duv[d];
            u64 ad[4], cd[4];
#pragma unroll
            for (int ii = 0; ii < 4; ii++) {
                float qu = Qu[(tm + ii) * 65 + d];
                ad[ii] = pdup_(qu);
                cd[ii] = pdup_(qu + duvd);
            }
            float bb0 = Kt[(tn + 0) * 65 + d], bb1 = Kt[(tn + 1) * 65 + d];
            float bb2 = Kt[(tn + 2) * 65 + d], bb3 = Kt[(tn + 3) * 65 + d];
            u64 kb0 = pack2_(bb0, bb1), kb1 = pack2_(bb2, bb3);
            float p7[7];
#pragma unroll
            for (int t = 0; t < 7; t++) p7[t] = Ps[d * 128 + base + t - 3];
            u64 pp[6];
#pragma unroll
            for (int t = 0; t < 6; t++) pp[t] = pack2_(p7[t], p7[t + 1]);
#pragma unroll
            for (int ii = 0; ii < 4; ii++) {
                acc2[ii][0] = ffma2_(ad[ii], kb0, acc2[ii][0]);
                acc2[ii][1] = ffma2_(ad[ii], kb1, acc2[ii][1]);
                acc2[ii][0] = ffma2_(cd[ii], pp[3 - ii], acc2[ii][0]);
                acc2[ii][1] = ffma2_(cd[ii], pp[5 - ii], acc2[ii][1]);
            }
        }

#pragma unroll
        for (int ii = 0; ii < 4; ii++) {
            float2 t0 = unpack2_(acc2[ii][0]);
            float2 t1 = unpack2_(acc2[ii][1]);
            float s0 = t0.x, s1 = t0.y, s2 = t1.x, s3 = t1.y;
            float mx = fmaxf(fmaxf(s0, s1), fmaxf(s2, s3));
#pragma unroll
            for (int o = 1; o < 16; o <<= 1)
                mx = fmaxf(mx, __shfl_xor_sync(0xffffffffu, mx, o));
            float mnew = fmaxf(mrow[ii], mx);
            float alpha = __expf(mrow[ii] - mnew);
            mrow[ii] = mnew;
            s0 = __expf(s0 - mnew); s1 = __expf(s1 - mnew);
            s2 = __expf(s2 - mnew); s3 = __expf(s3 - mnew);
            float rs = s0 + s1 + s2 + s3;
#pragma unroll
            for (int o = 1; o < 16; o <<= 1)
                rs += __shfl_xor_sync(0xffffffffu, rs, o);
            lrow[ii] = lrow[ii] * alpha + rs;
            u64 al = pdup_(alpha);
            outacc[ii][0] = mul2_(outacc[ii][0], al);
            outacc[ii][1] = mul2_(outacc[ii][1], al);
            *(float4*)&Es[(tm + ii) * 68 + tn] = make_float4(s0, s1, s2, s3);
        }
        __syncthreads();

#pragma unroll 8
        for (int kk = 0; kk < 64; kk++) {
            ulonglong2 bq = *(const ulonglong2*)&Vs[kk * 68 + tn];
#pragma unroll
            for (int ii = 0; ii < 4; ii++) {
                u64 a = pdup_(Es[(tm + ii) * 68 + kk]);
                outacc[ii][0] = ffma2_(a, bq.x, outacc[ii][0]);
                outacc[ii][1] = ffma2_(a, bq.y, outacc[ii][1]);
            }
        }
    }

#pragma unroll
    for (int ii = 0; ii < 4; ii++) {
        float inv = 1.f / lrow[ii];
        float2 t0 = unpack2_(outacc[ii][0]);
        float2 t1 = unpack2_(outacc[ii][1]);
        size_t off = (size_t)((i0 + tm + ii) * B_ + b) * E_ + h * 64 + tn;
        split2_(t0.x * inv, t0.y * inv, chi, clo, off);
        split2_(t1.x * inv, t1.y * inv, chi, clo, off + 2);
    }
}

// ---------------- GLU ----------------
__global__ void glu_kernel(const float* __restrict__ y, float* __restrict__ out)
{
    int idx = blockIdx.x * 256 + threadIdx.x;
    if (idx >= NTOK * E_) return;
    int r = idx >> 9, c = idx & 511;
    float a = y[(size_t)r * 1024 + c];
    float g = y[(size_t)r * 1024 + 512 + c];
    out[idx] = a * sigmoidf_(g);
}

// ---------------- depthwise conv + DoubleSwish -> split bf16 ----------------
__global__ void dwconv_kernel(const float* __restrict__ x, const float* __restrict__ w,
                              const float* __restrict__ bias,
                              __nv_bfloat16* __restrict__ ohi, __nv_bfloat16* __restrict__ olo)
{
    int idx = blockIdx.x * 256 + threadIdx.x;
    if (idx >= NTOK * E_) return;
    int c = idx & 511;
    int tb = idx >> 9;
    int t = tb >> 2, b = tb & 3;
    float acc = bias[c];
#pragma unroll
    for (int k = 0; k < KCONV; k++) {
        int tt = t + k - 15;
        if (tt >= 0 && tt < T_)
            acc += x[(size_t)(tt * B_ + b) * E_ + c] * w[c * KCONV + k];
    }
    float vv = acc * sigmoidf_(acc - 1.f);
    __nv_bfloat16 h = __float2bfloat16(vv);
    ohi[idx] = h;
    olo[idx] = __float2bfloat16(vv - __bfloat162float(h));
}

// ---------------- BasicNorm ----------------
__global__ void basic_norm_kernel(const float* __restrict__ x, const float* __restrict__ leps,
                                  float* __restrict__ out)
{
    __shared__ float red[8];
    const int tid = threadIdx.x;
    const float* p = x + (size_t)blockIdx.x * E_;
    float v0 = p[tid], v1 = p[tid + 256];
    float ss = v0 * v0 + v1 * v1;
#pragma unroll
    for (int o = 16; o > 0; o >>= 1) ss += __shfl_xor_sync(0xffffffffu, ss, o);
    if ((tid & 31) == 0) red[tid >> 5] = ss;
    __syncthreads();
    float tot = red[0];
#pragma unroll
    for (int i = 1; i < 8; i++) tot += red[i];
    float r = rsqrtf(tot * (1.f / (float)E_) + __expf(leps[0]));
    out[(size_t)blockIdx.x * E_ + tid]       = v0 * r;
    out[(size_t)blockIdx.x * E_ + tid + 256] = v1 * r;
}

// ---------------- launch ----------------
extern "C" void kernel_launch(void* const* d_in, const int* in_sizes, int n_in,
                              void* d_out, int out_size)
{
    const float* src      = (const float*)d_in[0];
    const float* pos_emb  = (const float*)d_in[1];
    const float* in_w     = (const float*)d_in[2];
    const float* in_b     = (const float*)d_in[3];
    const float* out_w    = (const float*)d_in[4];
    const float* out_b    = (const float*)d_in[5];
    const float* wpos     = (const float*)d_in[6];
    const float* u        = (const float*)d_in[7];
    const float* v        = (const float*)d_in[8];
    const float* ffm_w1   = (const float*)d_in[9];
    const float* ffm_b1   = (const float*)d_in[10];
    const float* ffm_w2   = (const float*)d_in[11];
    const float* ffm_b2   = (const float*)d_in[12];
    const float* ff_w1    = (const float*)d_in[13];
    const float* ff_b1    = (const float*)d_in[14];
    const float* ff_w2    = (const float*)d_in[15];
    const float* ff_b2    = (const float*)d_in[16];
    const float* pw1_w    = (const float*)d_in[17];
    const float* pw1_b    = (const float*)d_in[18];
    const float* dw_w     = (const float*)d_in[19];
    const float* dw_b     = (const float*)d_in[20];
    const float* pw2_w    = (const float*)d_in[21];
    const float* pw2_b    = (const float*)d_in[22];
    const float* leps     = (const float*)d_in[23];

    float *ff, *x1, *x2, *x3, *qkv, *pp, *glu;
    __nv_bfloat16 *whi, *wlo, *ahi, *alo, *bhi, *blo;
    cudaGetSymbolAddress((void**)&ff,  g_ff);
    cudaGetSymbolAddress((void**)&x1,  g_x1);
    cudaGetSymbolAddress((void**)&x2,  g_x2);
    cudaGetSymbolAddress((void**)&x3,  g_x3);
    cudaGetSymbolAddress((void**)&qkv, g_qkv);
    cudaGetSymbolAddress((void**)&pp,  g_pproj);
    cudaGetSymbolAddress((void**)&glu, g_glu);
    cudaGetSymbolAddress((void**)&whi, g_whi);
    cudaGetSymbolAddress((void**)&wlo, g_wlo);
    cudaGetSymbolAddress((void**)&ahi, g_ahi);
    cudaGetSymbolAddress((void**)&alo, g_alo);
    cudaGetSymbolAddress((void**)&bhi, g_bhi);
    cudaGetSymbolAddress((void**)&blo, g_blo);

    cudaFuncSetAttribute(attn_fused_kernel, cudaFuncAttributeMaxDynamicSharedMemorySize,
                         ATTN_SMEM);
#define SET_GSMEM(EPI, WC, WS) \
    cudaFuncSetAttribute((gemm_mma_kernel<EPI, WC, WS>), \
                         cudaFuncAttributeMaxDynamicSharedMemorySize, GEMM_SMEM_B)
    SET_GSMEM(EPI_DSWISH, 0, 1);
    SET_GSMEM(EPI_RES, 1, 1);
    SET_GSMEM(EPI_RES, 1, 0);
    SET_GSMEM(EPI_NONE, 1, 0);
#undef SET_GSMEM

    auto split = [&](const float* x, __nv_bfloat16* h, __nv_bfloat16* l, int n) {
        split_kernel<<<(n + 255) / 256, 256>>>(x, h, l, n);
    };

    // launches 0-4: splits (so launch #5, the FFN1 GEMM, is what ncu -s 5 captures)
    split(ffm_w1,  whi + OFF_FFM_W1, wlo + OFF_FFM_W1, DFF_ * E_);
    split(src, ahi, alo, NTOK * E_);
    split(ffm_w2,  whi + OFF_FFM_W2, wlo + OFF_FFM_W2, E_ * DFF_);
    split(in_w,    whi + OFF_IN_W,   wlo + OFF_IN_W,   3 * E_ * E_);
    split(wpos,    whi + OFF_WPOS,   wlo + OFF_WPOS,   E_ * E_);

    // 1) macaron FFN
    gemm_mma_kernel<EPI_DSWISH, 0, 1><<<dim3(DFF_ / 128, NTOK / 128), 256, GEMM_SMEM_B>>>(
        ahi, alo, whi + OFF_FFM_W1, wlo + OFF_FFM_W1, ffm_b1, nullptr,
        nullptr, bhi, blo, NTOK, DFF_, E_);
    gemm_mma_kernel<EPI_RES, 1, 1><<<dim3(E_ / 128, NTOK / 128), 256, GEMM_SMEM_B>>>(
        bhi, blo, whi + OFF_FFM_W2, wlo + OFF_FFM_W2, ffm_b2, src,
        x1, ahi, alo, NTOK, E_, DFF_);

    // 2) attention
    gemm_mma_kernel<EPI_NONE, 1, 0><<<dim3((3 * E_) / 128, NTOK / 128), 256, GEMM_SMEM_B>>>(
        ahi, alo, whi + OFF_IN_W, wlo + OFF_IN_W, in_b, nullptr,
        qkv, nullptr, nullptr, NTOK, 3 * E_, E_);
    split(pos_emb, whi + OFF_POSE, wlo + OFF_POSE, PLEN * E_);
    gemm_mma_kernel<EPI_NONE, 1, 0><<<dim3(E_ / 128, (PLEN + 127) / 128), 256, GEMM_SMEM_B>>>(
        whi + OFF_POSE, wlo + OFF_POSE, whi + OFF_WPOS, wlo + OFF_WPOS, nullptr, nullptr,
        pp, nullptr, nullptr, PLEN, E_, E_);
    attn_fused_kernel<<<dim3(T_ / 64, B_ * H_), 256, ATTN_SMEM>>>(qkv, pp, u, v, bhi, blo);
    split(out_w, whi + OFF_OUT_W, wlo + OFF_OUT_W, E_ * E_);
    gemm_mma_kernel<EPI_RES, 1, 1><<<dim3(E_ / 128, NTOK / 128), 256, GEMM_SMEM_B>>>(
        bhi, blo, whi + OFF_OUT_W, wlo + OFF_OUT_W, out_b, x1,
        x2, ahi, alo, NTOK, E_, E_);

    // 3) conv module
    split(pw1_w, whi + OFF_PW1_W, wlo + OFF_PW1_W, 2 * E_ * E_);
    gemm_mma_kernel<EPI_NONE, 1, 0><<<dim3((2 * E_) / 128, NTOK / 128), 256, GEMM_SMEM_B>>>(
        ahi, alo, whi + OFF_PW1_W, wlo + OFF_PW1_W, pw1_b, nullptr,
        ff, nullptr, nullptr, NTOK, 2 * E_, E_);
    glu_kernel<<<(NTOK * E_) / 256, 256>>>(ff, glu);
    dwconv_kernel<<<(NTOK * E_) / 256, 256>>>(glu, dw_w, dw_b, bhi, blo);
    split(pw2_w, whi + OFF_PW2_W, wlo + OFF_PW2_W, E_ * E_);
    gemm_mma_kernel<EPI_RES, 1, 1><<<dim3(E_ / 128, NTOK / 128), 256, GEMM_SMEM_B>>>(
        bhi, blo, whi + OFF_PW2_W, wlo + OFF_PW2_W, pw2_b, x2,
        x3, ahi, alo, NTOK, E_, E_);

    // 4) second FFN
    split(ff_w1, whi + OFF_FF_W1, wlo + OFF_FF_W1, DFF_ * E_);
    gemm_mma_kernel<EPI_DSWISH, 0, 1><<<dim3(DFF_ / 128, NTOK / 128), 256, GEMM_SMEM_B>>>(
        ahi, alo, whi + OFF_FF_W1, wlo + OFF_FF_W1, ff_b1, nullptr,
        nullptr, bhi, blo, NTOK, DFF_, E_);
    split(ff_w2, whi + OFF_FF_W2, wlo + OFF_FF_W2, E_ * DFF_);
    gemm_mma_kernel<EPI_RES, 1, 0><<<dim3(E_ / 128, NTOK / 128), 256, GEMM_SMEM_B>>>(
        bhi, blo, whi + OFF_FF_W2, wlo + OFF_FF_W2, ff_b2, x3,
        x1, nullptr, nullptr, NTOK, E_, DFF_);

    // 5) BasicNorm -> output
    basic_norm_kernel<<<NTOK, 256>>>(x1, leps, (float*)d_out);
}